// round 8
// baseline (speedup 1.0000x reference)
#include <cuda_runtime.h>
#include <cuda_fp16.h>
#include <math.h>
#include <stdint.h>

#define NP 100000
#define NA 50000
#define CDIM 128
#define CC (CDIM*CDIM)
#define NH 4
#define NPC (NP*CDIM)
#define EMAX 300000

#define PITCH 136                 // fp16 per row in staged images
#define PITCHB 272                // bytes
#define A_IMG 17408               // 64 rows * 272B  (per A image)
#define B_IMG 34816               // 128 rows * 272B (B image)
#define SLOT_U32 8704             // B image = 8704 u32 per slot
#define NSLOT 22                  // 0-9 layer0, 10-19 layer1, 20-21 wrapper

// ---------------- scratch (device globals) -----------------------------------
__device__ float  g_x[2][(NP+NA)*CDIM];
__device__ float  g_q[(NP+NA)*CDIM];
__device__ __half g_krel[3][NPC];
__device__ __half g_vrel[3][NPC];
__device__ float  g_agg[(NP+NA)*CDIM];
__device__ float  g_Wk[2][3][CC];
__device__ float  g_Wv[2][3][CC];
__device__ float  g_bk[2][3][CDIM];
__device__ float  g_bv[2][3][CDIM];
__device__ uint32_t g_wpack[NSLOT][SLOT_U32];
__device__ int g_rowptr[3][NP+1];
__device__ int g_csrc[3][EMAX];
__device__ int g_cnt[NP];
__device__ int g_bsum[64];

// ---------------- small helpers ----------------------------------------------
__device__ __forceinline__ float gelu_f(float x) {
    return 0.5f * x * (1.0f + erff(x * 0.7071067811865476f));
}
__global__ void fill_i(int* __restrict__ p, int v, int n) {
    int i = blockIdx.x * blockDim.x + threadIdx.x;
    if (i < n) p[i] = v;
}
__global__ void hist_k(const int* __restrict__ dst, int* __restrict__ cnt, int E) {
    int i = blockIdx.x * blockDim.x + threadIdx.x;
    if (i < E) atomicAdd(&cnt[dst[i]], 1);
}
__global__ void scan1(const int* __restrict__ cnt, int* __restrict__ rp1,
                      int* __restrict__ bsum, int n) {
    __shared__ int sm[256];
    int base = blockIdx.x * 4096;
    int idx0 = base + threadIdx.x * 16;
    int v[16]; int t = 0;
#pragma unroll
    for (int j = 0; j < 16; j++) { int ix = idx0 + j; v[j] = (ix < n) ? cnt[ix] : 0; t += v[j]; }
    sm[threadIdx.x] = t;
    __syncthreads();
    for (int off = 1; off < 256; off <<= 1) {
        int x = 0;
        if ((int)threadIdx.x >= off) x = sm[threadIdx.x - off];
        __syncthreads();
        if ((int)threadIdx.x >= off) sm[threadIdx.x] += x;
        __syncthreads();
    }
    int run = sm[threadIdx.x] - t;
#pragma unroll
    for (int j = 0; j < 16; j++) { run += v[j]; int ix = idx0 + j; if (ix < n) rp1[ix] = run; }
    if (threadIdx.x == 255) bsum[blockIdx.x] = sm[255];
}
__global__ void scan2(int* __restrict__ bsum, int nb) {
    int tid = threadIdx.x;
    int orig = (tid < nb) ? bsum[tid] : 0;
    int v = orig;
    for (int off = 1; off < 32; off <<= 1) {
        int x = __shfl_up_sync(0xffffffffu, v, off);
        if (tid >= off) v += x;
    }
    if (tid < nb) bsum[tid] = v - orig;
}
__global__ void scan3(int* __restrict__ rowptr, const int* __restrict__ bsum,
                      int* __restrict__ cursor, int n) {
    int i = blockIdx.x * blockDim.x + threadIdx.x;
    if (i < n) {
        int val = rowptr[i + 1] + bsum[i >> 12];
        rowptr[i + 1] = val;
        if (i + 1 < n) cursor[i + 1] = val;
    }
    if (i == 0) { rowptr[0] = 0; cursor[0] = 0; }
}
__global__ void csr_fill(const int* __restrict__ src, const int* __restrict__ dst,
                         int* __restrict__ cursor, int* __restrict__ csrc, int E) {
    int i = blockIdx.x * blockDim.x + threadIdx.x;
    if (i >= E) return;
    int pos = atomicAdd(&cursor[dst[i]], 1);
    csrc[pos] = src[i];
}

// ---------------- PTX helpers -------------------------------------------------
__device__ __forceinline__ uint32_t smem_u32(const void* p) {
    uint32_t a;
    asm("{ .reg .u64 t; cvta.to.shared.u64 t, %1; cvt.u32.u64 %0, t; }" : "=r"(a) : "l"(p));
    return a;
}
__device__ __forceinline__ uint32_t pk_h2(__half a, __half b) {
    __half2 t = __halves2half2(a, b);
    return *reinterpret_cast<uint32_t*>(&t);
}
__device__ __forceinline__ void ldsm4(uint32_t* r, uint32_t addr) {
    asm volatile("ldmatrix.sync.aligned.m8n8.x4.shared.b16 {%0,%1,%2,%3}, [%4];"
        : "=r"(r[0]), "=r"(r[1]), "=r"(r[2]), "=r"(r[3]) : "r"(addr));
}
__device__ __forceinline__ void mma16816(float* c, const uint32_t* a, const uint32_t* b) {
    asm volatile("mma.sync.aligned.m16n8k16.row.col.f32.f16.f16.f32 "
        "{%0,%1,%2,%3}, {%4,%5,%6,%7}, {%8,%9}, {%0,%1,%2,%3};"
        : "+f"(c[0]), "+f"(c[1]), "+f"(c[2]), "+f"(c[3])
        : "r"(a[0]), "r"(a[1]), "r"(a[2]), "r"(a[3]), "r"(b[0]), "r"(b[1]));
}
__device__ __forceinline__ void cp16(uint32_t dst, const void* src) {
    asm volatile("cp.async.cg.shared.global [%0], [%1], 16;" :: "r"(dst), "l"(src));
}

// ---------------- weight packing: fp32 -> pitched fp16 -------------------------
struct PackSrc { const float* w[NSLOT]; int count; };
__global__ void pack_weights(PackSrc ps, uint32_t* dstbase) {
    int m = blockIdx.x;
    if (m >= ps.count) return;
    const float* W = ps.w[m];
    uint32_t* hi = dstbase + (size_t)m * SLOT_U32;
    int n = threadIdx.x;
    int k0 = blockIdx.y * 16;
    for (int k = k0; k < k0 + 16; k += 2) {
        hi[n * (PITCH / 2) + (k >> 1)] =
            pk_h2(__float2half_rn(W[k * 128 + n]), __float2half_rn(W[(k + 1) * 128 + n]));
    }
}

// ---------------- composite relation weights (both layers) ---------------------
__global__ void build_comp(const float* __restrict__ kw0, const float* __restrict__ kb0,
                           const float* __restrict__ vw0, const float* __restrict__ vb0,
                           const float* __restrict__ arel0, const float* __restrict__ mrel0,
                           float* __restrict__ Wk0, float* __restrict__ bk0,
                           float* __restrict__ Wv0, float* __restrict__ bv0) {
    int c = blockIdx.x, r = blockIdx.y, l = blockIdx.z, j = threadIdx.x;
    const float* kw = kw0 + (size_t)l * 2 * CC;
    const float* kb = kb0 + l * 2 * CDIM;
    const float* vw = vw0 + (size_t)l * 2 * CC;
    const float* vb = vb0 + l * 2 * CDIM;
    const float* arel = arel0 + (size_t)l * 3 * NH * 1024;
    const float* mrel = mrel0 + (size_t)l * 3 * NH * 1024;
    float* Wk = Wk0 + (size_t)l * 3 * CC;
    float* Wv = Wv0 + (size_t)l * 3 * CC;
    float* bk = bk0 + l * 3 * CDIM;
    float* bv = bv0 + l * 3 * CDIM;
    int st = (r == 1) ? 1 : 0;
    int h = j >> 5, e = j & 31;
    const float* kwp = kw + ((size_t)st * CDIM + c) * CDIM + h * 32;
    const float* vwp = vw + ((size_t)st * CDIM + c) * CDIM + h * 32;
    const float* ap  = arel + (size_t)(r * NH + h) * 1024 + e;
    const float* mp  = mrel + (size_t)(r * NH + h) * 1024 + e;
    float sk = 0.f, sv = 0.f;
#pragma unroll
    for (int d = 0; d < 32; d++) {
        sk += kwp[d] * ap[d * 32];
        sv += vwp[d] * mp[d * 32];
    }
    Wk[(size_t)r * CC + (size_t)c * CDIM + j] = sk;
    Wv[(size_t)r * CC + (size_t)c * CDIM + j] = sv;
    if (c == 0) {
        float bks = 0.f, bvs = 0.f;
        const float* kbp = kb + st * CDIM + h * 32;
        const float* vbp = vb + st * CDIM + h * 32;
#pragma unroll
        for (int d = 0; d < 32; d++) {
            bks += kbp[d] * ap[d * 32];
            bvs += vbp[d] * mp[d * 32];
        }
        bk[r * CDIM + j] = bks;
        bv[r * CDIM + j] = bvs;
    }
}

// ---------------- tensor-core GEMM: fp16 2-term split, M-tile 64, 2 CTA/SM ----
struct TileArgs {
    const uint4* wp[5];
    const float* bias[5];
    void*        out[5];
    int          outHalf[5];   // 1: store fp16 (half2), 0: fp32
};

#define SM_A_HI  0
#define SM_A_LO  A_IMG
#define SM_B(b)  (2*A_IMG + (b)*B_IMG)
#define SM_NEED  (2*A_IMG + 2*B_IMG)     // 104448 bytes -> 2 CTAs/SM

__device__ __forceinline__ void prefetch_B(uint32_t dstb, const uint4* src, int tid) {
#pragma unroll
    for (int i = 0; i < 8; i++) cp16(dstb + (uint32_t)(i * 256 + tid) * 16, src + i * 256 + tid);
    if (tid < 128) cp16(dstb + (uint32_t)(2048 + tid) * 16, src + 2048 + tid);
    asm volatile("cp.async.commit_group;" ::: "memory");
}

__global__ void __launch_bounds__(256, 2)
gemm_mma(const float* __restrict__ A, TileArgs ta, int ntiles, int M,
         int aop, int eop, const float* __restrict__ xold, const float* __restrict__ skipp) {
    extern __shared__ char sm[];
    uint32_t sb = smem_u32(sm);
    int tid = threadIdx.x, lane = tid & 31, wid = tid >> 5;
    int wm = wid & 1, wn = wid >> 1;           // 2 m-warps x 4 n-warps (32x32 per warp)
    int rowBase = blockIdx.x * 64;

    prefetch_B(sb + SM_B(0), ta.wp[0], tid);

    // ---- stage A: fp32 -> gelu? -> fp16 hi/lo, pitched (64 rows) ----
#pragma unroll 4
    for (int it = 0; it < 8; it++) {
        int f = it * 256 + tid;
        int m = f >> 5, k = (f & 31) << 2;
        int row = rowBase + m;
        float4 v = make_float4(0.f, 0.f, 0.f, 0.f);
        if (row < M) v = *(const float4*)(A + (size_t)row * CDIM + k);
        if (aop) { v.x = gelu_f(v.x); v.y = gelu_f(v.y); v.z = gelu_f(v.z); v.w = gelu_f(v.w); }
        __half h0 = __float2half_rn(v.x), h1 = __float2half_rn(v.y);
        __half h2 = __float2half_rn(v.z), h3 = __float2half_rn(v.w);
        float r0 = v.x - __half2float(h0), r1 = v.y - __half2float(h1);
        float r2 = v.z - __half2float(h2), r3 = v.w - __half2float(h3);
        uint32_t off = (uint32_t)(m * PITCHB + k * 2);
        *(uint2*)(sm + SM_A_HI + off) = make_uint2(pk_h2(h0, h1), pk_h2(h2, h3));
        *(uint2*)(sm + SM_A_LO + off) = make_uint2(
            pk_h2(__float2half_rn(r0), __float2half_rn(r1)),
            pk_h2(__float2half_rn(r2), __float2half_rn(r3)));
    }

    int aRow = wm * 32 + (lane & 15);
    uint32_t aKoff = (lane & 16) ? 16u : 0u;
    uint32_t aBaseHi = sb + SM_A_HI + aRow * PITCHB + aKoff;
    uint32_t aBaseLo = aBaseHi + A_IMG;
    int bN = wn * 32 + (lane & 7) + ((lane & 16) ? 8 : 0);
    uint32_t bKoff = (lane & 8) ? 16u : 0u;
    uint32_t bOff = bN * PITCHB + bKoff;

    float skv = 0.f;
    if (eop == 2) skv = 1.f / (1.f + expf(-*skipp));
    int g = lane >> 2, tg = lane & 3;

    for (int b = 0; b < ntiles; b++) {
        if (b + 1 < ntiles) {
            prefetch_B(sb + SM_B((b + 1) & 1), ta.wp[b + 1], tid);
            asm volatile("cp.async.wait_group 1;" ::: "memory");
        } else {
            asm volatile("cp.async.wait_group 0;" ::: "memory");
        }
        __syncthreads();

        float acc[2][4][4];
#pragma unroll
        for (int i = 0; i < 2; i++)
#pragma unroll
            for (int j = 0; j < 4; j++)
#pragma unroll
                for (int q = 0; q < 4; q++) acc[i][j][q] = 0.f;

        uint32_t aHi = aBaseHi, aLo = aBaseLo, bHi = sb + SM_B(b & 1) + bOff;
#pragma unroll
        for (int ks = 0; ks < 8; ks++) {
            uint32_t ah[2][4], al[2][4], bh[2][4];
            ldsm4(ah[0], aHi); ldsm4(ah[1], aHi + 16 * PITCHB);
            ldsm4(al[0], aLo); ldsm4(al[1], aLo + 16 * PITCHB);
            ldsm4(bh[0], bHi); ldsm4(bh[1], bHi + 16 * PITCHB);
#pragma unroll
            for (int i = 0; i < 2; i++)
#pragma unroll
                for (int j = 0; j < 4; j++) {
                    const uint32_t* bp = &bh[j >> 1][(j & 1) * 2];
                    mma16816(acc[i][j], ah[i], bp);
                    mma16816(acc[i][j], al[i], bp);
                }
            aHi += 32; aLo += 32; bHi += 32;
        }
        __syncthreads();

        const float* bias = ta.bias[b];
        int oh = ta.outHalf[b];
        float* outF = (float*)ta.out[b];
        __half* outH = (__half*)ta.out[b];
#pragma unroll
        for (int i = 0; i < 2; i++) {
            int r0 = rowBase + wm * 32 + i * 16 + g;
#pragma unroll
            for (int j = 0; j < 4; j++) {
                int col = wn * 32 + j * 8 + tg * 2;
                float b0 = bias[col], b1 = bias[col + 1];
#pragma unroll
                for (int half = 0; half < 2; half++) {
                    int row = r0 + half * 8;
                    if (row >= M) continue;
                    float v0 = acc[i][j][half * 2 + 0] + b0;
                    float v1 = acc[i][j][half * 2 + 1] + b1;
                    if (eop == 1) {
                        v0 = fmaxf(v0, 0.f); v1 = fmaxf(v1, 0.f);
                    } else if (eop == 2) {
                        float2 xo = *(const float2*)(xold + (size_t)row * CDIM + col);
                        v0 = skv * v0 + (1.f - skv) * xo.x;
                        v1 = skv * v1 + (1.f - skv) * xo.y;
                    }
                    if (oh) {
                        *(__half2*)(outH + (size_t)row * CDIM + col) = __floats2half2_rn(v0, v1);
                    } else {
                        *(float2*)(outF + (size_t)row * CDIM + col) = make_float2(v0, v1);
                    }
                }
            }
        }
    }
}

// ---------------- edge phase: CSR gather + online softmax (fp16 k/v) -----------
__device__ __forceinline__ float4 ld_half4(const __half* base, size_t off) {
    uint2 raw = *(const uint2*)(base + off);
    __half2* ph = (__half2*)&raw;
    float2 a = __half22float2(ph[0]);
    float2 b = __half22float2(ph[1]);
    return make_float4(a.x, a.y, b.x, b.y);
}

__global__ void __launch_bounds__(256)
edge_gather(const float* __restrict__ q, float* __restrict__ agg, int N, int nrel,
            const __half* __restrict__ kr0, const __half* __restrict__ vr0,
            const int* __restrict__ rp0, const int* __restrict__ cs0,
            const float* __restrict__ pr0,
            const __half* __restrict__ kr1, const __half* __restrict__ vr1,
            const int* __restrict__ rp1, const int* __restrict__ cs1,
            const float* __restrict__ pr1) {
    int w = (blockIdx.x * blockDim.x + threadIdx.x) >> 5;
    if (w >= N) return;
    int lane = threadIdx.x & 31;
    int h = lane >> 3;
    float4 qv = *(const float4*)(q + (size_t)w * CDIM + lane * 4);
    float4 tot = make_float4(0.f, 0.f, 0.f, 0.f);
    for (int rel = 0; rel < nrel; rel++) {
        const __half* kr = rel ? kr1 : kr0;
        const __half* vr = rel ? vr1 : vr0;
        const int* rp = rel ? rp1 : rp0;
        const int* cs = rel ? cs1 : cs0;
        const float* prl = rel ? pr1 : pr0;
        float pscale = prl[h] * 0.17677669529663687f;
        int beg = rp[w], end = rp[w + 1];
        float m = -INFINITY, s = 0.f;
        float4 acc = make_float4(0.f, 0.f, 0.f, 0.f);
        float4 kv, vv;
        if (beg < end) {
            int sidx = cs[beg];
            kv = ld_half4(kr, (size_t)sidx * CDIM + lane * 4);
            vv = ld_half4(vr, (size_t)sidx * CDIM + lane * 4);
        }
        for (int e = beg; e < end; e++) {
            float4 kn, vn;
            if (e + 1 < end) {
                int sn = cs[e + 1];
                kn = ld_half4(kr, (size_t)sn * CDIM + lane * 4);
                vn = ld_half4(vr, (size_t)sn * CDIM + lane * 4);
            }
            float dot = qv.x * kv.x + qv.y * kv.y + qv.z * kv.z + qv.w * kv.w;
            dot += __shfl_xor_sync(0xffffffffu, dot, 1);
            dot += __shfl_xor_sync(0xffffffffu, dot, 2);
            dot += __shfl_xor_sync(0xffffffffu, dot, 4);
            float alpha = dot * pscale;
            float mn = fmaxf(m, alpha);
            float sc = __expf(m - mn);
            float p = __expf(alpha - mn);
            s = s * sc + p;
            acc.x = acc.x * sc + p * vv.x;
            acc.y = acc.y * sc + p * vv.y;
            acc.z = acc.z * sc + p * vv.z;
            acc.w = acc.w * sc + p * vv.w;
            m = mn;
            kv = kn; vv = vn;
        }
        float inv = 1.f / (s + 1e-16f);
        tot.x += acc.x * inv; tot.y += acc.y * inv;
        tot.z += acc.z * inv; tot.w += acc.w * inv;
    }
    *(float4*)(agg + (size_t)w * CDIM + lane * 4) = tot;
}

// ---------------- host orchestration -------------------------------------------
extern "C" void kernel_launch(void* const* d_in, const int* in_sizes, int n_in,
                              void* d_out, int out_size) {
    const float* x_paper  = (const float*)d_in[0];
    const float* x_author = (const float*)d_in[1];
    const float* lin_w = (const float*)d_in[2];
    const float* lin_b = (const float*)d_in[3];
    const float* k_w = (const float*)d_in[4];
    const float* k_b = (const float*)d_in[5];
    const float* q_w = (const float*)d_in[6];
    const float* q_b = (const float*)d_in[7];
    const float* v_w = (const float*)d_in[8];
    const float* v_b = (const float*)d_in[9];
    const float* a_w = (const float*)d_in[10];
    const float* a_b = (const float*)d_in[11];
    const float* skip  = (const float*)d_in[12];
    const float* a_rel = (const float*)d_in[13];
    const float* m_rel = (const float*)d_in[14];
    const float* p_rel = (const float*)d_in[15];
    const int* srcs[3] = {(const int*)d_in[16], (const int*)d_in[18], (const int*)d_in[20]};
    const int* dsts[3] = {(const int*)d_in[17], (const int*)d_in[19], (const int*)d_in[21]};
    int E[3] = {in_sizes[16], in_sizes[18], in_sizes[20]};

    static cudaStream_t s1 = nullptr;
    static cudaEvent_t ev[12];
    if (!s1) {
        cudaStreamCreateWithFlags(&s1, cudaStreamNonBlocking);
        for (int i = 0; i < 12; i++) cudaEventCreateWithFlags(&ev[i], cudaEventDisableTiming);
        cudaFuncSetAttribute(gemm_mma, cudaFuncAttributeMaxDynamicSharedMemorySize, SM_NEED);
    }
    cudaStream_t s0 = 0;
    int evi = 0;
    auto forkTo1 = [&]() { cudaEventRecord(ev[evi], s0); cudaStreamWaitEvent(s1, ev[evi], 0); evi++; };
    auto joinTo0 = [&]() { cudaEventRecord(ev[evi], s1); cudaStreamWaitEvent(s0, ev[evi], 0); evi++; };

    void* p;
    float *xb[2], *qb, *agg, *Wk, *Wv, *bk, *bv;
    __half *krel, *vrel;
    uint32_t* wpack;
    int *rowptr[3], *csrc[3], *cnt, *bsum;
    cudaGetSymbolAddress(&p, g_x);    xb[0] = (float*)p; xb[1] = xb[0] + (size_t)(NP + NA) * CDIM;
    cudaGetSymbolAddress(&p, g_q);    qb    = (float*)p;
    cudaGetSymbolAddress(&p, g_krel); krel  = (__half*)p;
    cudaGetSymbolAddress(&p, g_vrel); vrel  = (__half*)p;
    cudaGetSymbolAddress(&p, g_agg);  agg   = (float*)p;
    cudaGetSymbolAddress(&p, g_Wk);   Wk    = (float*)p;
    cudaGetSymbolAddress(&p, g_Wv);   Wv    = (float*)p;
    cudaGetSymbolAddress(&p, g_bk);   bk    = (float*)p;
    cudaGetSymbolAddress(&p, g_bv);   bv    = (float*)p;
    cudaGetSymbolAddress(&p, g_wpack);wpack = (uint32_t*)p;
    cudaGetSymbolAddress(&p, g_rowptr);
    for (int r = 0; r < 3; r++) rowptr[r] = (int*)p + (size_t)r * (NP + 1);
    cudaGetSymbolAddress(&p, g_csrc);
    for (int r = 0; r < 3; r++) csrc[r] = (int*)p + (size_t)r * EMAX;
    cudaGetSymbolAddress(&p, g_cnt);  cnt  = (int*)p;
    cudaGetSymbolAddress(&p, g_bsum); bsum = (int*)p;

    auto slot = [&](int s) { return (const uint4*)(wpack + (size_t)s * SLOT_U32); };
    auto run_gemm = [&](cudaStream_t st, const float* A, TileArgs& ta, int nt, int M,
                        int aop, int eop, const float* xold, const float* sp) {
        gemm_mma<<<(M + 63) / 64, 256, SM_NEED, st>>>(A, ta, nt, M, aop, eop, xold, sp);
    };

    // ======== fork: CSR build entirely on s1 ========
    forkTo1();
    for (int r = 0; r < 3; r++) {
        int Nd = (r == 2) ? NA : NP;
        fill_i<<<(Nd + 255) / 256, 256, 0, s1>>>(cnt, 0, Nd);
        hist_k<<<(E[r] + 255) / 256, 256, 0, s1>>>(dsts[r], cnt, E[r]);
        int nb = (Nd + 4095) / 4096;
        scan1<<<nb, 256, 0, s1>>>(cnt, rowptr[r] + 1, bsum, Nd);
        scan2<<<1, 32, 0, s1>>>(bsum, nb);
        scan3<<<(Nd + 255) / 256, 256, 0, s1>>>(rowptr[r], bsum, cnt, Nd);
        csr_fill<<<(E[r] + 255) / 256, 256, 0, s1>>>(srcs[r], dsts[r], cnt, csrc[r], E[r]);
    }

    // ======== s0: composite weights (both layers) + pack ALL 22 slots ==========
    build_comp<<<dim3(CDIM, 3, 2), CDIM, 0, s0>>>(k_w, k_b, v_w, v_b, a_rel, m_rel,
                                                  Wk, bk, Wv, bv);
    {
        PackSrc ps{};
        for (int l = 0; l < 2; l++) {
            int base = l * 10;
            ps.w[base + 0] = q_w + (size_t)(l * 2 + 0) * CC;
            ps.w[base + 1] = q_w + (size_t)(l * 2 + 1) * CC;
            ps.w[base + 2] = Wk + (size_t)(l * 3 + 0) * CC;
            ps.w[base + 3] = Wv + (size_t)(l * 3 + 0) * CC;
            ps.w[base + 4] = Wk + (size_t)(l * 3 + 2) * CC;
            ps.w[base + 5] = Wv + (size_t)(l * 3 + 2) * CC;
            ps.w[base + 6] = Wk + (size_t)(l * 3 + 1) * CC;
            ps.w[base + 7] = Wv + (size_t)(l * 3 + 1) * CC;
            ps.w[base + 8] = a_w + (size_t)(l * 2 + 0) * CC;
            ps.w[base + 9] = a_w + (size_t)(l * 2 + 1) * CC;
        }
        ps.w[20] = lin_w; ps.w[21] = lin_w + CC;
        ps.count = NSLOT;
        pack_weights<<<dim3(NSLOT, 8), 128, 0, s0>>>(ps, wpack);
    }

    // ======== wrapper GEMMs: paper on s0, author on s1 =========================
    forkTo1();
    {
        TileArgs ta{};
        ta.wp[0] = slot(20); ta.bias[0] = lin_b; ta.out[0] = xb[0]; ta.outHalf[0] = 0;
        run_gemm(s0, x_paper, ta, 1, NP, 0, 1, nullptr, nullptr);
        TileArgs tb{};
        tb.wp[0] = slot(21); tb.bias[0] = lin_b + CDIM; tb.out[0] = xb[0] + NPC; tb.outHalf[0] = 0;
        run_gemm(s1, x_author, tb, 1, NA, 0, 1, nullptr, nullptr);
    }

    int cur = 0;
    for (int l = 0; l < 2; l++) {
        int sl = l * 10;
        const float* bkL = bk + l * 3 * CDIM;
        const float* bvL = bv + l * 3 * CDIM;

        // s1: author fused gemm: q_a | krel1 | vrel1
        {
            TileArgs ta{};
            ta.wp[0] = slot(sl + 1); ta.bias[0] = q_b + (l * 2 + 1) * CDIM;
            ta.out[0] = qb + NPC;               ta.outHalf[0] = 0;
            ta.wp[1] = slot(sl + 6); ta.bias[1] = bkL + CDIM;
            ta.out[1] = krel + (size_t)NPC;     ta.outHalf[1] = 1;
            ta.wp[2] = slot(sl + 7); ta.bias[2] = bvL + CDIM;
            ta.out[2] = vrel + (size_t)NPC;     ta.outHalf[2] = 1;
            run_gemm(s1, xb[cur] + NPC, ta, 3, NA, 0, 0, nullptr, nullptr);
        }
        // s0: paper fused gemm: q_p | krel0 | vrel0 | krel2 | vrel2
        {
            TileArgs ta{};
            ta.wp[0] = slot(sl + 0); ta.bias[0] = q_b + (l * 2 + 0) * CDIM;
            ta.out[0] = qb;                     ta.outHalf[0] = 0;
            ta.wp[1] = slot(sl + 2); ta.bias[1] = bkL;
            ta.out[1] = krel;                   ta.outHalf[1] = 1;
            ta.wp[2] = slot(sl + 3); ta.bias[2] = bvL;
            ta.out[2] = vrel;                   ta.outHalf[2] = 1;
            ta.wp[3] = slot(sl + 4); ta.bias[3] = bkL + 2 * CDIM;
            ta.out[3] = krel + 2 * (size_t)NPC; ta.outHalf[3] = 1;
            ta.wp[4] = slot(sl + 5); ta.bias[4] = bvL + 2 * CDIM;
            ta.out[4] = vrel + 2 * (size_t)NPC; ta.outHalf[4] = 1;
            run_gemm(s0, xb[cur], ta, 5, NP, 0, 0, nullptr, nullptr);
        }

        joinTo0();   // author gemm results (krel1/vrel1) -> s0 gather
        forkTo1();   // paper gemm results (krel2/vrel2)  -> s1 gather

        edge_gather<<<(NP * 32 + 255) / 256, 256, 0, s0>>>(
            qb, agg, NP, 2,
            krel, vrel, rowptr[0], csrc[0], p_rel + (size_t)(l * 3 + 0) * NH,
            krel + (size_t)NPC, vrel + (size_t)NPC, rowptr[1], csrc[1],
            p_rel + (size_t)(l * 3 + 1) * NH);
        edge_gather<<<(NA * 32 + 255) / 256, 256, 0, s1>>>(
            qb + NPC, agg + NPC, NA, 1,
            krel + 2 * (size_t)NPC, vrel + 2 * (size_t)NPC, rowptr[2], csrc[2],
            p_rel + (size_t)(l * 3 + 2) * NH,
            nullptr, nullptr, nullptr, nullptr, nullptr);

        {
            float* outp = (l == 1) ? (float*)d_out : xb[1 - cur];
            TileArgs ta{};
            ta.wp[0] = slot(sl + 8); ta.bias[0] = a_b + (l * 2 + 0) * CDIM;
            ta.out[0] = outp; ta.outHalf[0] = 0;
            run_gemm(s0, agg, ta, 1, NP, 1, 2, xb[cur], skip + l * 2 + 0);
        }
        {
            float* outp = ((l == 1) ? (float*)d_out : xb[1 - cur]) + NPC;
            TileArgs ta{};
            ta.wp[0] = slot(sl + 9); ta.bias[0] = a_b + (l * 2 + 1) * CDIM;
            ta.out[0] = outp; ta.outHalf[0] = 0;
            run_gemm(s1, agg + NPC, ta, 1, NA, 1, 2, xb[cur] + NPC, skip + l * 2 + 1);
        }

        joinTo0();
        if (l == 0) forkTo1();
        cur = 1 - cur;
    }
}

// round 9
// speedup vs baseline: 1.1334x; 1.1334x over previous
#include <cuda_runtime.h>
#include <cuda_fp16.h>
#include <math.h>
#include <stdint.h>

#define NP 100000
#define NA 50000
#define CDIM 128
#define CC (CDIM*CDIM)
#define NH 4
#define NPC (NP*CDIM)
#define EMAX 300000

#define PITCH 136                 // fp16 per row in staged images
#define PITCHB 272                // bytes
#define A_IMG 17408               // 64 rows * 272B
#define B_IMG 34816               // 128 rows * 272B
#define SLOT_U32 8704             // B image = 8704 u32 per slot
#define NSLOT 22                  // 0-9 layer0, 10-19 layer1, 20-21 wrapper

// ---------------- scratch (device globals) -----------------------------------
__device__ float  g_x[2][(NP+NA)*CDIM];
__device__ float  g_q[(NP+NA)*CDIM];
__device__ __half g_krel[3][NPC];
__device__ __half g_vrel[3][NPC];
__device__ float  g_agg[(NP+NA)*CDIM];
__device__ float  g_Wk[2][3][CC];
__device__ float  g_Wv[2][3][CC];
__device__ float  g_bk[2][3][CDIM];
__device__ float  g_bv[2][3][CDIM];
__device__ uint32_t g_wpack[NSLOT][SLOT_U32];
__device__ int g_rowptr[3][NP+1];
__device__ int g_csrc[3][EMAX];
__device__ int g_cnt[NP];
__device__ int g_bsum[64];

// ---------------- small helpers ----------------------------------------------
__device__ __forceinline__ float gelu_f(float x) {
    return 0.5f * x * (1.0f + erff(x * 0.7071067811865476f));
}
__global__ void fill_i(int* __restrict__ p, int v, int n) {
    int i = blockIdx.x * blockDim.x + threadIdx.x;
    if (i < n) p[i] = v;
}
__global__ void hist_k(const int* __restrict__ dst, int* __restrict__ cnt, int E) {
    int i = blockIdx.x * blockDim.x + threadIdx.x;
    if (i < E) atomicAdd(&cnt[dst[i]], 1);
}
__global__ void scan1(const int* __restrict__ cnt, int* __restrict__ rp1,
                      int* __restrict__ bsum, int n) {
    __shared__ int sm[256];
    int base = blockIdx.x * 4096;
    int idx0 = base + threadIdx.x * 16;
    int v[16]; int t = 0;
#pragma unroll
    for (int j = 0; j < 16; j++) { int ix = idx0 + j; v[j] = (ix < n) ? cnt[ix] : 0; t += v[j]; }
    sm[threadIdx.x] = t;
    __syncthreads();
    for (int off = 1; off < 256; off <<= 1) {
        int x = 0;
        if ((int)threadIdx.x >= off) x = sm[threadIdx.x - off];
        __syncthreads();
        if ((int)threadIdx.x >= off) sm[threadIdx.x] += x;
        __syncthreads();
    }
    int run = sm[threadIdx.x] - t;
#pragma unroll
    for (int j = 0; j < 16; j++) { run += v[j]; int ix = idx0 + j; if (ix < n) rp1[ix] = run; }
    if (threadIdx.x == 255) bsum[blockIdx.x] = sm[255];
}
__global__ void scan2(int* __restrict__ bsum, int nb) {
    int tid = threadIdx.x;
    int orig = (tid < nb) ? bsum[tid] : 0;
    int v = orig;
    for (int off = 1; off < 32; off <<= 1) {
        int x = __shfl_up_sync(0xffffffffu, v, off);
        if (tid >= off) v += x;
    }
    if (tid < nb) bsum[tid] = v - orig;
}
__global__ void scan3(int* __restrict__ rowptr, const int* __restrict__ bsum,
                      int* __restrict__ cursor, int n) {
    int i = blockIdx.x * blockDim.x + threadIdx.x;
    if (i < n) {
        int val = rowptr[i + 1] + bsum[i >> 12];
        rowptr[i + 1] = val;
        if (i + 1 < n) cursor[i + 1] = val;
    }
    if (i == 0) { rowptr[0] = 0; cursor[0] = 0; }
}
__global__ void csr_fill(const int* __restrict__ src, const int* __restrict__ dst,
                         int* __restrict__ cursor, int* __restrict__ csrc, int E) {
    int i = blockIdx.x * blockDim.x + threadIdx.x;
    if (i >= E) return;
    int pos = atomicAdd(&cursor[dst[i]], 1);
    csrc[pos] = src[i];
}

// ---------------- PTX helpers -------------------------------------------------
__device__ __forceinline__ uint32_t smem_u32(const void* p) {
    uint32_t a;
    asm("{ .reg .u64 t; cvta.to.shared.u64 t, %1; cvt.u32.u64 %0, t; }" : "=r"(a) : "l"(p));
    return a;
}
__device__ __forceinline__ uint32_t pk_h2(__half a, __half b) {
    __half2 t = __halves2half2(a, b);
    return *reinterpret_cast<uint32_t*>(&t);
}
__device__ __forceinline__ void ldsm4(uint32_t* r, uint32_t addr) {
    asm volatile("ldmatrix.sync.aligned.m8n8.x4.shared.b16 {%0,%1,%2,%3}, [%4];"
        : "=r"(r[0]), "=r"(r[1]), "=r"(r[2]), "=r"(r[3]) : "r"(addr));
}
__device__ __forceinline__ void mma16816(float* c, const uint32_t* a, const uint32_t* b) {
    asm volatile("mma.sync.aligned.m16n8k16.row.col.f32.f16.f16.f32 "
        "{%0,%1,%2,%3}, {%4,%5,%6,%7}, {%8,%9}, {%0,%1,%2,%3};"
        : "+f"(c[0]), "+f"(c[1]), "+f"(c[2]), "+f"(c[3])
        : "r"(a[0]), "r"(a[1]), "r"(a[2]), "r"(a[3]), "r"(b[0]), "r"(b[1]));
}
__device__ __forceinline__ void cp16(uint32_t dst, const void* src) {
    asm volatile("cp.async.cg.shared.global [%0], [%1], 16;" :: "r"(dst), "l"(src));
}

// ---------------- weight packing: fp32 -> pitched fp16 -------------------------
struct PackSrc { const float* w[NSLOT]; int count; };
__global__ void pack_weights(PackSrc ps, uint32_t* dstbase) {
    int m = blockIdx.x;
    if (m >= ps.count) return;
    const float* W = ps.w[m];
    uint32_t* hi = dstbase + (size_t)m * SLOT_U32;
    int n = threadIdx.x;
    int k0 = blockIdx.y * 16;
    for (int k = k0; k < k0 + 16; k += 2) {
        hi[n * (PITCH / 2) + (k >> 1)] =
            pk_h2(__float2half_rn(W[k * 128 + n]), __float2half_rn(W[(k + 1) * 128 + n]));
    }
}

// ---------------- composite relation weights (both layers) ---------------------
__global__ void build_comp(const float* __restrict__ kw0, const float* __restrict__ kb0,
                           const float* __restrict__ vw0, const float* __restrict__ vb0,
                           const float* __restrict__ arel0, const float* __restrict__ mrel0,
                           float* __restrict__ Wk0, float* __restrict__ bk0,
                           float* __restrict__ Wv0, float* __restrict__ bv0) {
    int c = blockIdx.x, r = blockIdx.y, l = blockIdx.z, j = threadIdx.x;
    const float* kw = kw0 + (size_t)l * 2 * CC;
    const float* kb = kb0 + l * 2 * CDIM;
    const float* vw = vw0 + (size_t)l * 2 * CC;
    const float* vb = vb0 + l * 2 * CDIM;
    const float* arel = arel0 + (size_t)l * 3 * NH * 1024;
    const float* mrel = mrel0 + (size_t)l * 3 * NH * 1024;
    float* Wk = Wk0 + (size_t)l * 3 * CC;
    float* Wv = Wv0 + (size_t)l * 3 * CC;
    float* bk = bk0 + l * 3 * CDIM;
    float* bv = bv0 + l * 3 * CDIM;
    int st = (r == 1) ? 1 : 0;
    int h = j >> 5, e = j & 31;
    const float* kwp = kw + ((size_t)st * CDIM + c) * CDIM + h * 32;
    const float* vwp = vw + ((size_t)st * CDIM + c) * CDIM + h * 32;
    const float* ap  = arel + (size_t)(r * NH + h) * 1024 + e;
    const float* mp  = mrel + (size_t)(r * NH + h) * 1024 + e;
    float sk = 0.f, sv = 0.f;
#pragma unroll
    for (int d = 0; d < 32; d++) {
        sk += kwp[d] * ap[d * 32];
        sv += vwp[d] * mp[d * 32];
    }
    Wk[(size_t)r * CC + (size_t)c * CDIM + j] = sk;
    Wv[(size_t)r * CC + (size_t)c * CDIM + j] = sv;
    if (c == 0) {
        float bks = 0.f, bvs = 0.f;
        const float* kbp = kb + st * CDIM + h * 32;
        const float* vbp = vb + st * CDIM + h * 32;
#pragma unroll
        for (int d = 0; d < 32; d++) {
            bks += kbp[d] * ap[d * 32];
            bvs += vbp[d] * mp[d * 32];
        }
        bk[r * CDIM + j] = bks;
        bv[r * CDIM + j] = bvs;
    }
}

// ---------------- tensor-core GEMM: single-pass fp16, M-tile 64, 2 CTA/SM -----
struct TileArgs {
    const uint4* wp[5];
    const float* bias[5];
    void*        out[5];
    int          outHalf[5];   // 1: store fp16 (half2), 0: fp32
};

#define SM_A     0
#define SM_B(b)  (A_IMG + (b)*B_IMG)
#define SM_NEED  (A_IMG + 2*B_IMG)       // 87040 bytes -> 2 CTAs/SM

__device__ __forceinline__ void prefetch_B(uint32_t dstb, const uint4* src, int tid) {
#pragma unroll
    for (int i = 0; i < 8; i++) cp16(dstb + (uint32_t)(i * 256 + tid) * 16, src + i * 256 + tid);
    if (tid < 128) cp16(dstb + (uint32_t)(2048 + tid) * 16, src + 2048 + tid);
    asm volatile("cp.async.commit_group;" ::: "memory");
}

__global__ void __launch_bounds__(256, 2)
gemm_mma(const float* __restrict__ A, TileArgs ta, int ntiles, int M,
         int aop, int eop, const float* __restrict__ xold, const float* __restrict__ skipp) {
    extern __shared__ char sm[];
    uint32_t sb = smem_u32(sm);
    int tid = threadIdx.x, lane = tid & 31, wid = tid >> 5;
    int wm = wid & 1, wn = wid >> 1;           // 2 m-warps x 4 n-warps (32x32 per warp)
    int rowBase = blockIdx.x * 64;

    prefetch_B(sb + SM_B(0), ta.wp[0], tid);

    // ---- stage A: fp32 -> gelu? -> fp16, pitched (64 rows) ----
#pragma unroll 4
    for (int it = 0; it < 8; it++) {
        int f = it * 256 + tid;
        int m = f >> 5, k = (f & 31) << 2;
        int row = rowBase + m;
        float4 v = make_float4(0.f, 0.f, 0.f, 0.f);
        if (row < M) v = *(const float4*)(A + (size_t)row * CDIM + k);
        if (aop) { v.x = gelu_f(v.x); v.y = gelu_f(v.y); v.z = gelu_f(v.z); v.w = gelu_f(v.w); }
        uint32_t off = (uint32_t)(m * PITCHB + k * 2);
        *(uint2*)(sm + SM_A + off) = make_uint2(
            pk_h2(__float2half_rn(v.x), __float2half_rn(v.y)),
            pk_h2(__float2half_rn(v.z), __float2half_rn(v.w)));
    }

    int aRow = wm * 32 + (lane & 15);
    uint32_t aKoff = (lane & 16) ? 16u : 0u;
    uint32_t aBase = sb + SM_A + aRow * PITCHB + aKoff;
    int bN = wn * 32 + (lane & 7) + ((lane & 16) ? 8 : 0);
    uint32_t bKoff = (lane & 8) ? 16u : 0u;
    uint32_t bOff = bN * PITCHB + bKoff;

    float skv = 0.f;
    if (eop == 2) skv = 1.f / (1.f + expf(-*skipp));
    int g = lane >> 2, tg = lane & 3;

    for (int b = 0; b < ntiles; b++) {
        if (b + 1 < ntiles) {
            prefetch_B(sb + SM_B((b + 1) & 1), ta.wp[b + 1], tid);
            asm volatile("cp.async.wait_group 1;" ::: "memory");
        } else {
            asm volatile("cp.async.wait_group 0;" ::: "memory");
        }
        __syncthreads();

        float acc[2][4][4];
#pragma unroll
        for (int i = 0; i < 2; i++)
#pragma unroll
            for (int j = 0; j < 4; j++)
#pragma unroll
                for (int q = 0; q < 4; q++) acc[i][j][q] = 0.f;

        uint32_t aCur = aBase, bHi = sb + SM_B(b & 1) + bOff;
#pragma unroll
        for (int ks = 0; ks < 8; ks++) {
            uint32_t ah[2][4], bh[2][4];
            ldsm4(ah[0], aCur); ldsm4(ah[1], aCur + 16 * PITCHB);
            ldsm4(bh[0], bHi);  ldsm4(bh[1], bHi + 16 * PITCHB);
#pragma unroll
            for (int i = 0; i < 2; i++)
#pragma unroll
                for (int j = 0; j < 4; j++)
                    mma16816(acc[i][j], ah[i], &bh[j >> 1][(j & 1) * 2]);
            aCur += 32; bHi += 32;
        }
        __syncthreads();

        const float* bias = ta.bias[b];
        int oh = ta.outHalf[b];
        float* outF = (float*)ta.out[b];
        __half* outH = (__half*)ta.out[b];
#pragma unroll
        for (int i = 0; i < 2; i++) {
            int r0 = rowBase + wm * 32 + i * 16 + g;
#pragma unroll
            for (int j = 0; j < 4; j++) {
                int col = wn * 32 + j * 8 + tg * 2;
                float b0 = bias[col], b1 = bias[col + 1];
#pragma unroll
                for (int half = 0; half < 2; half++) {
                    int row = r0 + half * 8;
                    if (row >= M) continue;
                    float v0 = acc[i][j][half * 2 + 0] + b0;
                    float v1 = acc[i][j][half * 2 + 1] + b1;
                    if (eop == 1) {
                        v0 = fmaxf(v0, 0.f); v1 = fmaxf(v1, 0.f);
                    } else if (eop == 2) {
                        float2 xo = *(const float2*)(xold + (size_t)row * CDIM + col);
                        v0 = skv * v0 + (1.f - skv) * xo.x;
                        v1 = skv * v1 + (1.f - skv) * xo.y;
                    }
                    if (oh) {
                        *(__half2*)(outH + (size_t)row * CDIM + col) = __floats2half2_rn(v0, v1);
                    } else {
                        *(float2*)(outF + (size_t)row * CDIM + col) = make_float2(v0, v1);
                    }
                }
            }
        }
    }
}

// ---------------- edge phase: CSR gather + online softmax (fp16 k/v) -----------
__device__ __forceinline__ float4 ld_half4(const __half* base, size_t off) {
    uint2 raw = *(const uint2*)(base + off);
    __half2* ph = (__half2*)&raw;
    float2 a = __half22float2(ph[0]);
    float2 b = __half22float2(ph[1]);
    return make_float4(a.x, a.y, b.x, b.y);
}

__global__ void __launch_bounds__(256)
edge_gather(const float* __restrict__ q, float* __restrict__ agg, int N, int nrel,
            const __half* __restrict__ kr0, const __half* __restrict__ vr0,
            const int* __restrict__ rp0, const int* __restrict__ cs0,
            const float* __restrict__ pr0,
            const __half* __restrict__ kr1, const __half* __restrict__ vr1,
            const int* __restrict__ rp1, const int* __restrict__ cs1,
            const float* __restrict__ pr1) {
    int w = (blockIdx.x * blockDim.x + threadIdx.x) >> 5;
    if (w >= N) return;
    int lane = threadIdx.x & 31;
    int h = lane >> 3;
    float4 qv = *(const float4*)(q + (size_t)w * CDIM + lane * 4);
    float4 tot = make_float4(0.f, 0.f, 0.f, 0.f);
    for (int rel = 0; rel < nrel; rel++) {
        const __half* kr = rel ? kr1 : kr0;
        const __half* vr = rel ? vr1 : vr0;
        const int* rp = rel ? rp1 : rp0;
        const int* cs = rel ? cs1 : cs0;
        const float* prl = rel ? pr1 : pr0;
        float pscale = prl[h] * 0.17677669529663687f;
        int beg = rp[w], end = rp[w + 1];
        float m = -INFINITY, s = 0.f;
        float4 acc = make_float4(0.f, 0.f, 0.f, 0.f);
        float4 kv, vv;
        if (beg < end) {
            int sidx = cs[beg];
            kv = ld_half4(kr, (size_t)sidx * CDIM + lane * 4);
            vv = ld_half4(vr, (size_t)sidx * CDIM + lane * 4);
        }
        for (int e = beg; e < end; e++) {
            float4 kn, vn;
            if (e + 1 < end) {
                int sn = cs[e + 1];
                kn = ld_half4(kr, (size_t)sn * CDIM + lane * 4);
                vn = ld_half4(vr, (size_t)sn * CDIM + lane * 4);
            }
            float dot = qv.x * kv.x + qv.y * kv.y + qv.z * kv.z + qv.w * kv.w;
            dot += __shfl_xor_sync(0xffffffffu, dot, 1);
            dot += __shfl_xor_sync(0xffffffffu, dot, 2);
            dot += __shfl_xor_sync(0xffffffffu, dot, 4);
            float alpha = dot * pscale;
            float mn = fmaxf(m, alpha);
            float sc = __expf(m - mn);
            float p = __expf(alpha - mn);
            s = s * sc + p;
            acc.x = acc.x * sc + p * vv.x;
            acc.y = acc.y * sc + p * vv.y;
            acc.z = acc.z * sc + p * vv.z;
            acc.w = acc.w * sc + p * vv.w;
            m = mn;
            kv = kn; vv = vn;
        }
        float inv = 1.f / (s + 1e-16f);
        tot.x += acc.x * inv; tot.y += acc.y * inv;
        tot.z += acc.z * inv; tot.w += acc.w * inv;
    }
    *(float4*)(agg + (size_t)w * CDIM + lane * 4) = tot;
}

// ---------------- host orchestration -------------------------------------------
extern "C" void kernel_launch(void* const* d_in, const int* in_sizes, int n_in,
                              void* d_out, int out_size) {
    const float* x_paper  = (const float*)d_in[0];
    const float* x_author = (const float*)d_in[1];
    const float* lin_w = (const float*)d_in[2];
    const float* lin_b = (const float*)d_in[3];
    const float* k_w = (const float*)d_in[4];
    const float* k_b = (const float*)d_in[5];
    const float* q_w = (const float*)d_in[6];
    const float* q_b = (const float*)d_in[7];
    const float* v_w = (const float*)d_in[8];
    const float* v_b = (const float*)d_in[9];
    const float* a_w = (const float*)d_in[10];
    const float* a_b = (const float*)d_in[11];
    const float* skip  = (const float*)d_in[12];
    const float* a_rel = (const float*)d_in[13];
    const float* m_rel = (const float*)d_in[14];
    const float* p_rel = (const float*)d_in[15];
    const int* srcs[3] = {(const int*)d_in[16], (const int*)d_in[18], (const int*)d_in[20]};
    const int* dsts[3] = {(const int*)d_in[17], (const int*)d_in[19], (const int*)d_in[21]};
    int E[3] = {in_sizes[16], in_sizes[18], in_sizes[20]};

    static cudaStream_t s1 = nullptr;
    static cudaEvent_t ev[12];
    if (!s1) {
        cudaStreamCreateWithFlags(&s1, cudaStreamNonBlocking);
        for (int i = 0; i < 12; i++) cudaEventCreateWithFlags(&ev[i], cudaEventDisableTiming);
        cudaFuncSetAttribute(gemm_mma, cudaFuncAttributeMaxDynamicSharedMemorySize, SM_NEED);
    }
    cudaStream_t s0 = 0;
    int evi = 0;
    auto forkTo1 = [&]() { cudaEventRecord(ev[evi], s0); cudaStreamWaitEvent(s1, ev[evi], 0); evi++; };
    auto joinTo0 = [&]() { cudaEventRecord(ev[evi], s1); cudaStreamWaitEvent(s0, ev[evi], 0); evi++; };

    void* p;
    float *xb[2], *qb, *agg, *Wk, *Wv, *bk, *bv;
    __half *krel, *vrel;
    uint32_t* wpack;
    int *rowptr[3], *csrc[3], *cnt, *bsum;
    cudaGetSymbolAddress(&p, g_x);    xb[0] = (float*)p; xb[1] = xb[0] + (size_t)(NP + NA) * CDIM;
    cudaGetSymbolAddress(&p, g_q);    qb    = (float*)p;
    cudaGetSymbolAddress(&p, g_krel); krel  = (__half*)p;
    cudaGetSymbolAddress(&p, g_vrel); vrel  = (__half*)p;
    cudaGetSymbolAddress(&p, g_agg);  agg   = (float*)p;
    cudaGetSymbolAddress(&p, g_Wk);   Wk    = (float*)p;
    cudaGetSymbolAddress(&p, g_Wv);   Wv    = (float*)p;
    cudaGetSymbolAddress(&p, g_bk);   bk    = (float*)p;
    cudaGetSymbolAddress(&p, g_bv);   bv    = (float*)p;
    cudaGetSymbolAddress(&p, g_wpack);wpack = (uint32_t*)p;
    cudaGetSymbolAddress(&p, g_rowptr);
    for (int r = 0; r < 3; r++) rowptr[r] = (int*)p + (size_t)r * (NP + 1);
    cudaGetSymbolAddress(&p, g_csrc);
    for (int r = 0; r < 3; r++) csrc[r] = (int*)p + (size_t)r * EMAX;
    cudaGetSymbolAddress(&p, g_cnt);  cnt  = (int*)p;
    cudaGetSymbolAddress(&p, g_bsum); bsum = (int*)p;

    auto slot = [&](int s) { return (const uint4*)(wpack + (size_t)s * SLOT_U32); };
    auto run_gemm = [&](cudaStream_t st, const float* A, TileArgs& ta, int nt, int M,
                        int aop, int eop, const float* xold, const float* sp) {
        gemm_mma<<<(M + 63) / 64, 256, SM_NEED, st>>>(A, ta, nt, M, aop, eop, xold, sp);
    };

    // ======== fork: CSR build entirely on s1 ========
    forkTo1();
    for (int r = 0; r < 3; r++) {
        int Nd = (r == 2) ? NA : NP;
        fill_i<<<(Nd + 255) / 256, 256, 0, s1>>>(cnt, 0, Nd);
        hist_k<<<(E[r] + 255) / 256, 256, 0, s1>>>(dsts[r], cnt, E[r]);
        int nb = (Nd + 4095) / 4096;
        scan1<<<nb, 256, 0, s1>>>(cnt, rowptr[r] + 1, bsum, Nd);
        scan2<<<1, 32, 0, s1>>>(bsum, nb);
        scan3<<<(Nd + 255) / 256, 256, 0, s1>>>(rowptr[r], bsum, cnt, Nd);
        csr_fill<<<(E[r] + 255) / 256, 256, 0, s1>>>(srcs[r], dsts[r], cnt, csrc[r], E[r]);
    }

    // ======== s0: composite weights (both layers) + pack ALL 22 slots ==========
    build_comp<<<dim3(CDIM, 3, 2), CDIM, 0, s0>>>(k_w, k_b, v_w, v_b, a_rel, m_rel,
                                                  Wk, bk, Wv, bv);
    {
        PackSrc ps{};
        for (int l = 0; l < 2; l++) {
            int base = l * 10;
            ps.w[base + 0] = q_w + (size_t)(l * 2 + 0) * CC;
            ps.w[base + 1] = q_w + (size_t)(l * 2 + 1) * CC;
            ps.w[base + 2] = Wk + (size_t)(l * 3 + 0) * CC;
            ps.w[base + 3] = Wv + (size_t)(l * 3 + 0) * CC;
            ps.w[base + 4] = Wk + (size_t)(l * 3 + 2) * CC;
            ps.w[base + 5] = Wv + (size_t)(l * 3 + 2) * CC;
            ps.w[base + 6] = Wk + (size_t)(l * 3 + 1) * CC;
            ps.w[base + 7] = Wv + (size_t)(l * 3 + 1) * CC;
            ps.w[base + 8] = a_w + (size_t)(l * 2 + 0) * CC;
            ps.w[base + 9] = a_w + (size_t)(l * 2 + 1) * CC;
        }
        ps.w[20] = lin_w; ps.w[21] = lin_w + CC;
        ps.count = NSLOT;
        pack_weights<<<dim3(NSLOT, 8), 128, 0, s0>>>(ps, wpack);
    }

    // ======== wrapper GEMMs: paper on s0, author on s1 =========================
    forkTo1();
    {
        TileArgs ta{};
        ta.wp[0] = slot(20); ta.bias[0] = lin_b; ta.out[0] = xb[0]; ta.outHalf[0] = 0;
        run_gemm(s0, x_paper, ta, 1, NP, 0, 1, nullptr, nullptr);
        TileArgs tb{};
        tb.wp[0] = slot(21); tb.bias[0] = lin_b + CDIM; tb.out[0] = xb[0] + NPC; tb.outHalf[0] = 0;
        run_gemm(s1, x_author, tb, 1, NA, 0, 1, nullptr, nullptr);
    }

    int cur = 0;
    for (int l = 0; l < 2; l++) {
        int sl = l * 10;
        const float* bkL = bk + l * 3 * CDIM;
        const float* bvL = bv + l * 3 * CDIM;

        // s1: author fused gemm: q_a | krel1 | vrel1
        {
            TileArgs ta{};
            ta.wp[0] = slot(sl + 1); ta.bias[0] = q_b + (l * 2 + 1) * CDIM;
            ta.out[0] = qb + NPC;               ta.outHalf[0] = 0;
            ta.wp[1] = slot(sl + 6); ta.bias[1] = bkL + CDIM;
            ta.out[1] = krel + (size_t)NPC;     ta.outHalf[1] = 1;
            ta.wp[2] = slot(sl + 7); ta.bias[2] = bvL + CDIM;
            ta.out[2] = vrel + (size_t)NPC;     ta.outHalf[2] = 1;
            run_gemm(s1, xb[cur] + NPC, ta, 3, NA, 0, 0, nullptr, nullptr);
        }
        // s0: paper fused gemm: q_p | krel0 | vrel0 | krel2 | vrel2
        {
            TileArgs ta{};
            ta.wp[0] = slot(sl + 0); ta.bias[0] = q_b + (l * 2 + 0) * CDIM;
            ta.out[0] = qb;                     ta.outHalf[0] = 0;
            ta.wp[1] = slot(sl + 2); ta.bias[1] = bkL;
            ta.out[1] = krel;                   ta.outHalf[1] = 1;
            ta.wp[2] = slot(sl + 3); ta.bias[2] = bvL;
            ta.out[2] = vrel;                   ta.outHalf[2] = 1;
            ta.wp[3] = slot(sl + 4); ta.bias[3] = bkL + 2 * CDIM;
            ta.out[3] = krel + 2 * (size_t)NPC; ta.outHalf[3] = 1;
            ta.wp[4] = slot(sl + 5); ta.bias[4] = bvL + 2 * CDIM;
            ta.out[4] = vrel + 2 * (size_t)NPC; ta.outHalf[4] = 1;
            run_gemm(s0, xb[cur], ta, 5, NP, 0, 0, nullptr, nullptr);
        }

        joinTo0();   // author gemm results (krel1/vrel1) -> s0 gather
        forkTo1();   // paper gemm results (krel2/vrel2)  -> s1 gather

        edge_gather<<<(NP * 32 + 255) / 256, 256, 0, s0>>>(
            qb, agg, NP, 2,
            krel, vrel, rowptr[0], csrc[0], p_rel + (size_t)(l * 3 + 0) * NH,
            krel + (size_t)NPC, vrel + (size_t)NPC, rowptr[1], csrc[1],
            p_rel + (size_t)(l * 3 + 1) * NH);
        edge_gather<<<(NA * 32 + 255) / 256, 256, 0, s1>>>(
            qb + NPC, agg + NPC, NA, 1,
            krel + 2 * (size_t)NPC, vrel + 2 * (size_t)NPC, rowptr[2], csrc[2],
            p_rel + (size_t)(l * 3 + 2) * NH,
            nullptr, nullptr, nullptr, nullptr, nullptr);

        {
            float* outp = (l == 1) ? (float*)d_out : xb[1 - cur];
            TileArgs ta{};
            ta.wp[0] = slot(sl + 8); ta.bias[0] = a_b + (l * 2 + 0) * CDIM;
            ta.out[0] = outp; ta.outHalf[0] = 0;
            run_gemm(s0, agg, ta, 1, NP, 1, 2, xb[cur], skip + l * 2 + 0);
        }
        {
            float* outp = ((l == 1) ? (float*)d_out : xb[1 - cur]) + NPC;
            TileArgs ta{};
            ta.wp[0] = slot(sl + 9); ta.bias[0] = a_b + (l * 2 + 1) * CDIM;
            ta.out[0] = outp; ta.outHalf[0] = 0;
            run_gemm(s1, agg + NPC, ta, 1, NA, 1, 2, xb[cur] + NPC, skip + l * 2 + 1);
        }

        joinTo0();
        if (l == 0) forkTo1();
        cur = 1 - cur;
    }
}

// round 10
// speedup vs baseline: 1.1433x; 1.0088x over previous
#include <cuda_runtime.h>
#include <cuda_fp16.h>
#include <math.h>
#include <stdint.h>

#define NP 100000
#define NA 50000
#define CDIM 128
#define CC (CDIM*CDIM)
#define NH 4
#define NPC (NP*CDIM)
#define EMAX 300000

#define PITCH 136                 // fp16 per row in staged images
#define PITCHB 272                // bytes
#define A_IMG 17408               // 64 rows * 272B
#define B_IMG 34816               // 128 rows * 272B
#define SLOT_U32 8704             // one B image = 8704 u32 per slot
#define NSLOT 22                  // 0-9 layer0, 10-19 layer1, 20-21 wrapper
#define CTAS_P ((NP+63)/64)       // 1563
#define CTAS_A ((NA+63)/64)       // 782

// ---------------- scratch (device globals) -----------------------------------
__device__ float  g_x[2][(NP+NA)*CDIM];
__device__ float  g_q[(NP+NA)*CDIM];
__device__ __half g_krel[3][NPC];
__device__ __half g_vrel[3][NPC];
__device__ float  g_agg[(NP+NA)*CDIM];
__device__ float  g_Wk[2][3][CC];
__device__ float  g_Wv[2][3][CC];
__device__ float  g_bk[2][3][CDIM];
__device__ float  g_bv[2][3][CDIM];
__device__ uint32_t g_wpack[NSLOT][SLOT_U32];
__device__ int g_rowptr[3][NP+1];
__device__ int g_csrc[3][EMAX];
__device__ int g_cnt[NP];
__device__ int g_bsum[64];

// ---------------- small helpers ----------------------------------------------
__device__ __forceinline__ float gelu_f(float x) {
    return 0.5f * x * (1.0f + erff(x * 0.7071067811865476f));
}
__global__ void fill_i(int* __restrict__ p, int v, int n) {
    int i = blockIdx.x * blockDim.x + threadIdx.x;
    if (i < n) p[i] = v;
}
__global__ void hist_k(const int* __restrict__ dst, int* __restrict__ cnt, int E) {
    int i = blockIdx.x * blockDim.x + threadIdx.x;
    if (i < E) atomicAdd(&cnt[dst[i]], 1);
}
__global__ void scan1(const int* __restrict__ cnt, int* __restrict__ rp1,
                      int* __restrict__ bsum, int n) {
    __shared__ int sm[256];
    int base = blockIdx.x * 4096;
    int idx0 = base + threadIdx.x * 16;
    int v[16]; int t = 0;
#pragma unroll
    for (int j = 0; j < 16; j++) { int ix = idx0 + j; v[j] = (ix < n) ? cnt[ix] : 0; t += v[j]; }
    sm[threadIdx.x] = t;
    __syncthreads();
    for (int off = 1; off < 256; off <<= 1) {
        int x = 0;
        if ((int)threadIdx.x >= off) x = sm[threadIdx.x - off];
        __syncthreads();
        if ((int)threadIdx.x >= off) sm[threadIdx.x] += x;
        __syncthreads();
    }
    int run = sm[threadIdx.x] - t;
#pragma unroll
    for (int j = 0; j < 16; j++) { run += v[j]; int ix = idx0 + j; if (ix < n) rp1[ix] = run; }
    if (threadIdx.x == 255) bsum[blockIdx.x] = sm[255];
}
__global__ void scan2(int* __restrict__ bsum, int nb) {
    int tid = threadIdx.x;
    int orig = (tid < nb) ? bsum[tid] : 0;
    int v = orig;
    for (int off = 1; off < 32; off <<= 1) {
        int x = __shfl_up_sync(0xffffffffu, v, off);
        if (tid >= off) v += x;
    }
    if (tid < nb) bsum[tid] = v - orig;
}
__global__ void scan3(int* __restrict__ rowptr, const int* __restrict__ bsum,
                      int* __restrict__ cursor, int n) {
    int i = blockIdx.x * blockDim.x + threadIdx.x;
    if (i < n) {
        int val = rowptr[i + 1] + bsum[i >> 12];
        rowptr[i + 1] = val;
        if (i + 1 < n) cursor[i + 1] = val;
    }
    if (i == 0) { rowptr[0] = 0; cursor[0] = 0; }
}
__global__ void csr_fill(const int* __restrict__ src, const int* __restrict__ dst,
                         int* __restrict__ cursor, int* __restrict__ csrc, int E) {
    int i = blockIdx.x * blockDim.x + threadIdx.x;
    if (i >= E) return;
    int pos = atomicAdd(&cursor[dst[i]], 1);
    csrc[pos] = src[i];
}

// ---------------- PTX helpers -------------------------------------------------
__device__ __forceinline__ uint32_t smem_u32(const void* p) {
    uint32_t a;
    asm("{ .reg .u64 t; cvta.to.shared.u64 t, %1; cvt.u32.u64 %0, t; }" : "=r"(a) : "l"(p));
    return a;
}
__device__ __forceinline__ uint32_t pk_h2(__half a, __half b) {
    __half2 t = __halves2half2(a, b);
    return *reinterpret_cast<uint32_t*>(&t);
}
__device__ __forceinline__ void ldsm4(uint32_t* r, uint32_t addr) {
    asm volatile("ldmatrix.sync.aligned.m8n8.x4.shared.b16 {%0,%1,%2,%3}, [%4];"
        : "=r"(r[0]), "=r"(r[1]), "=r"(r[2]), "=r"(r[3]) : "r"(addr));
}
__device__ __forceinline__ void mma16816(float* c, const uint32_t* a, const uint32_t* b) {
    asm volatile("mma.sync.aligned.m16n8k16.row.col.f32.f16.f16.f32 "
        "{%0,%1,%2,%3}, {%4,%5,%6,%7}, {%8,%9}, {%0,%1,%2,%3};"
        : "+f"(c[0]), "+f"(c[1]), "+f"(c[2]), "+f"(c[3])
        : "r"(a[0]), "r"(a[1]), "r"(a[2]), "r"(a[3]), "r"(b[0]), "r"(b[1]));
}
__device__ __forceinline__ void cp16(uint32_t dst, const void* src) {
    asm volatile("cp.async.cg.shared.global [%0], [%1], 16;" :: "r"(dst), "l"(src));
}

// ---------------- weight packing: fp32 -> pitched fp16 -------------------------
struct PackSrc { const float* w[NSLOT]; int count; };
__global__ void pack_weights(PackSrc ps, uint32_t* dstbase) {
    int m = blockIdx.x;
    if (m >= ps.count) return;
    const float* W = ps.w[m];
    uint32_t* hi = dstbase + (size_t)m * SLOT_U32;
    int n = threadIdx.x;
    int k0 = blockIdx.y * 16;
    for (int k = k0; k < k0 + 16; k += 2) {
        hi[n * (PITCH / 2) + (k >> 1)] =
            pk_h2(__float2half_rn(W[k * 128 + n]), __float2half_rn(W[(k + 1) * 128 + n]));
    }
}

// ---------------- composite relation weights (both layers) ---------------------
__global__ void build_comp(const float* __restrict__ kw0, const float* __restrict__ kb0,
                           const float* __restrict__ vw0, const float* __restrict__ vb0,
                           const float* __restrict__ arel0, const float* __restrict__ mrel0,
                           float* __restrict__ Wk0, float* __restrict__ bk0,
                           float* __restrict__ Wv0, float* __restrict__ bv0) {
    int c = blockIdx.x, r = blockIdx.y, l = blockIdx.z, j = threadIdx.x;
    const float* kw = kw0 + (size_t)l * 2 * CC;
    const float* kb = kb0 + l * 2 * CDIM;
    const float* vw = vw0 + (size_t)l * 2 * CC;
    const float* vb = vb0 + l * 2 * CDIM;
    const float* arel = arel0 + (size_t)l * 3 * NH * 1024;
    const float* mrel = mrel0 + (size_t)l * 3 * NH * 1024;
    float* Wk = Wk0 + (size_t)l * 3 * CC;
    float* Wv = Wv0 + (size_t)l * 3 * CC;
    float* bk = bk0 + l * 3 * CDIM;
    float* bv = bv0 + l * 3 * CDIM;
    int st = (r == 1) ? 1 : 0;
    int h = j >> 5, e = j & 31;
    const float* kwp = kw + ((size_t)st * CDIM + c) * CDIM + h * 32;
    const float* vwp = vw + ((size_t)st * CDIM + c) * CDIM + h * 32;
    const float* ap  = arel + (size_t)(r * NH + h) * 1024 + e;
    const float* mp  = mrel + (size_t)(r * NH + h) * 1024 + e;
    float sk = 0.f, sv = 0.f;
#pragma unroll
    for (int d = 0; d < 32; d++) {
        sk += kwp[d] * ap[d * 32];
        sv += vwp[d] * mp[d * 32];
    }
    Wk[(size_t)r * CC + (size_t)c * CDIM + j] = sk;
    Wv[(size_t)r * CC + (size_t)c * CDIM + j] = sv;
    if (c == 0) {
        float bks = 0.f, bvs = 0.f;
        const float* kbp = kb + st * CDIM + h * 32;
        const float* vbp = vb + st * CDIM + h * 32;
#pragma unroll
        for (int d = 0; d < 32; d++) {
            bks += kbp[d] * ap[d * 32];
            bvs += vbp[d] * mp[d * 32];
        }
        bk[r * CDIM + j] = bks;
        bv[r * CDIM + j] = bvs;
    }
}

// ---------------- segmented chained mega-GEMM ----------------------------------
// Per-segment descriptor. Tile 0 may be "chained": its epilogue output is also
// re-staged (fp16, pitched) into the smem A image, feeding tiles 1..ntiles-1.
struct GemmSeg {
    const float* A;
    const float* xold;     // for eop==2 tiles
    const float* skipp;    // sigmoid gate scalar (may be null)
    int M;
    int ntiles;
    int chain;             // 1: tile0 output becomes new A
    const uint4* wp[6];
    const float* bias[6];
    void*        out[6];
    int          outHalf[6];  // 1: fp16 output
    int          eop[6];      // 0 +bias, 1 relu, 2 skip-blend
};

#define SM_A     0
#define SM_B(b)  (A_IMG + (b)*B_IMG)
#define SM_NEED  (A_IMG + 2*B_IMG)       // 87040 bytes -> 2 CTAs/SM

__device__ __forceinline__ void prefetch_B(uint32_t dstb, const uint4* src, int tid) {
#pragma unroll
    for (int i = 0; i < 8; i++) cp16(dstb + (uint32_t)(i * 256 + tid) * 16, src + i * 256 + tid);
    if (tid < 128) cp16(dstb + (uint32_t)(2048 + tid) * 16, src + 2048 + tid);
    asm volatile("cp.async.commit_group;" ::: "memory");
}

__global__ void __launch_bounds__(256, 2)
gemm_mega(GemmSeg P0, GemmSeg P1, int ctas0, int aop) {
    extern __shared__ char sm[];
    uint32_t sb = smem_u32(sm);
    int tid = threadIdx.x, lane = tid & 31, wid = tid >> 5;
    int wm = wid & 1, wn = wid >> 1;           // 2 m-warps x 4 n-warps
    int bx = blockIdx.x;
    bool seg1 = bx >= ctas0;
    const GemmSeg& P = seg1 ? P1 : P0;
    int rowBase = (seg1 ? bx - ctas0 : bx) * 64;
    int M = P.M;
    const float* A = P.A;

    prefetch_B(sb + SM_B(0), P.wp[0], tid);

    // ---- stage A: fp32 -> gelu? -> fp16, pitched (64 rows) ----
#pragma unroll 4
    for (int it = 0; it < 8; it++) {
        int f = it * 256 + tid;
        int m = f >> 5, k = (f & 31) << 2;
        int row = rowBase + m;
        float4 v = make_float4(0.f, 0.f, 0.f, 0.f);
        if (row < M) v = *(const float4*)(A + (size_t)row * CDIM + k);
        if (aop) { v.x = gelu_f(v.x); v.y = gelu_f(v.y); v.z = gelu_f(v.z); v.w = gelu_f(v.w); }
        uint32_t off = (uint32_t)(m * PITCHB + k * 2);
        *(uint2*)(sm + SM_A + off) = make_uint2(
            pk_h2(__float2half_rn(v.x), __float2half_rn(v.y)),
            pk_h2(__float2half_rn(v.z), __float2half_rn(v.w)));
    }

    int aRow = wm * 32 + (lane & 15);
    uint32_t aKoff = (lane & 16) ? 16u : 0u;
    uint32_t aBase = sb + SM_A + aRow * PITCHB + aKoff;
    int bN = wn * 32 + (lane & 7) + ((lane & 16) ? 8 : 0);
    uint32_t bKoff = (lane & 8) ? 16u : 0u;
    uint32_t bOff = bN * PITCHB + bKoff;

    float skv = 0.f;
    if (P.skipp) skv = 1.f / (1.f + expf(-*P.skipp));
    int g = lane >> 2, tg = lane & 3;
    int nt = P.ntiles;

    for (int b = 0; b < nt; b++) {
        if (b + 1 < nt) {
            prefetch_B(sb + SM_B((b + 1) & 1), P.wp[b + 1], tid);
            asm volatile("cp.async.wait_group 1;" ::: "memory");
        } else {
            asm volatile("cp.async.wait_group 0;" ::: "memory");
        }
        __syncthreads();   // B ready; also orders prior epilogue/chain writes

        float acc[2][4][4];
#pragma unroll
        for (int i = 0; i < 2; i++)
#pragma unroll
            for (int j = 0; j < 4; j++)
#pragma unroll
                for (int q = 0; q < 4; q++) acc[i][j][q] = 0.f;

        uint32_t aCur = aBase, bHi = sb + SM_B(b & 1) + bOff;
#pragma unroll
        for (int ks = 0; ks < 8; ks++) {
            uint32_t ah[2][4], bh[2][4];
            ldsm4(ah[0], aCur); ldsm4(ah[1], aCur + 16 * PITCHB);
            ldsm4(bh[0], bHi);  ldsm4(bh[1], bHi + 16 * PITCHB);
#pragma unroll
            for (int i = 0; i < 2; i++)
#pragma unroll
                for (int j = 0; j < 4; j++)
                    mma16816(acc[i][j], ah[i], &bh[j >> 1][(j & 1) * 2]);
            aCur += 32; bHi += 32;
        }
        __syncthreads();   // all A/B reads done before epilogue may rewrite A

        const float* bias = P.bias[b];
        int eop = P.eop[b];
        int oh = P.outHalf[b];
        bool chain0 = (b == 0) && P.chain;
        float* outF = (float*)P.out[b];
        __half* outH = (__half*)P.out[b];
#pragma unroll
        for (int i = 0; i < 2; i++) {
            int r0 = rowBase + wm * 32 + i * 16 + g;
#pragma unroll
            for (int j = 0; j < 4; j++) {
                int col = wn * 32 + j * 8 + tg * 2;
                float b0 = bias[col], b1 = bias[col + 1];
#pragma unroll
                for (int half = 0; half < 2; half++) {
                    int row = r0 + half * 8;
                    if (row >= M) continue;
                    float v0 = acc[i][j][half * 2 + 0] + b0;
                    float v1 = acc[i][j][half * 2 + 1] + b1;
                    if (eop == 1) {
                        v0 = fmaxf(v0, 0.f); v1 = fmaxf(v1, 0.f);
                    } else if (eop == 2) {
                        float2 xo = *(const float2*)(P.xold + (size_t)row * CDIM + col);
                        v0 = skv * v0 + (1.f - skv) * xo.x;
                        v1 = skv * v1 + (1.f - skv) * xo.y;
                    }
                    if (oh) {
                        *(__half2*)(outH + (size_t)row * CDIM + col) = __floats2half2_rn(v0, v1);
                    } else {
                        *(float2*)(outF + (size_t)row * CDIM + col) = make_float2(v0, v1);
                    }
                    if (chain0) {
                        uint32_t off = (uint32_t)((row - rowBase) * PITCHB + col * 2);
                        *(__half2*)(sm + SM_A + off) = __floats2half2_rn(v0, v1);
                    }
                }
            }
        }
        // next iteration's top __syncthreads orders chain writes before ldsm
    }
}

// ---------------- merged edge gather: all nodes, online softmax ---------------
__device__ __forceinline__ float4 ld_half4(const __half* base, size_t off) {
    uint2 raw = *(const uint2*)(base + off);
    __half2* ph = (__half2*)&raw;
    float2 a = __half22float2(ph[0]);
    float2 b = __half22float2(ph[1]);
    return make_float4(a.x, a.y, b.x, b.y);
}

__global__ void __launch_bounds__(256)
gather_all(const float* __restrict__ q, float* __restrict__ agg,
           const __half* __restrict__ krel, const __half* __restrict__ vrel,
           const int* __restrict__ rp0, const int* __restrict__ cs0,
           const int* __restrict__ rp1, const int* __restrict__ cs1,
           const int* __restrict__ rp2, const int* __restrict__ cs2,
           const float* __restrict__ prel) {
    int w = (blockIdx.x * blockDim.x + threadIdx.x) >> 5;
    if (w >= NP + NA) return;
    int lane = threadIdx.x & 31;
    int h = lane >> 3;
    float4 qv = *(const float4*)(q + (size_t)w * CDIM + lane * 4);
    float4 tot = make_float4(0.f, 0.f, 0.f, 0.f);
    int nrel, node;
    const int* rps[2]; const int* css[2]; int rr[2];
    if (w < NP) {
        nrel = 2; node = w;
        rps[0] = rp0; css[0] = cs0; rr[0] = 0;
        rps[1] = rp1; css[1] = cs1; rr[1] = 1;
    } else {
        nrel = 1; node = w - NP;
        rps[0] = rp2; css[0] = cs2; rr[0] = 2;
        rps[1] = rp2; css[1] = cs2; rr[1] = 2;
    }
    for (int rel = 0; rel < nrel; rel++) {
        const __half* kr = krel + (size_t)rr[rel] * NPC;
        const __half* vr = vrel + (size_t)rr[rel] * NPC;
        const int* rp = rps[rel];
        const int* cs = css[rel];
        float pscale = prel[rr[rel] * NH + h] * 0.17677669529663687f;
        int beg = rp[node], end = rp[node + 1];
        float m = -INFINITY, s = 0.f;
        float4 acc = make_float4(0.f, 0.f, 0.f, 0.f);
        float4 kv, vv;
        if (beg < end) {
            int sidx = cs[beg];
            kv = ld_half4(kr, (size_t)sidx * CDIM + lane * 4);
            vv = ld_half4(vr, (size_t)sidx * CDIM + lane * 4);
        }
        for (int e = beg; e < end; e++) {
            float4 kn, vn;
            if (e + 1 < end) {
                int sn = cs[e + 1];
                kn = ld_half4(kr, (size_t)sn * CDIM + lane * 4);
                vn = ld_half4(vr, (size_t)sn * CDIM + lane * 4);
            }
            float dot = qv.x * kv.x + qv.y * kv.y + qv.z * kv.z + qv.w * kv.w;
            dot += __shfl_xor_sync(0xffffffffu, dot, 1);
            dot += __shfl_xor_sync(0xffffffffu, dot, 2);
            dot += __shfl_xor_sync(0xffffffffu, dot, 4);
            float alpha = dot * pscale;
            float mn = fmaxf(m, alpha);
            float sc = __expf(m - mn);
            float p = __expf(alpha - mn);
            s = s * sc + p;
            acc.x = acc.x * sc + p * vv.x;
            acc.y = acc.y * sc + p * vv.y;
            acc.z = acc.z * sc + p * vv.z;
            acc.w = acc.w * sc + p * vv.w;
            m = mn;
            kv = kn; vv = vn;
        }
        float inv = 1.f / (s + 1e-16f);
        tot.x += acc.x * inv; tot.y += acc.y * inv;
        tot.z += acc.z * inv; tot.w += acc.w * inv;
    }
    *(float4*)(agg + (size_t)w * CDIM + lane * 4) = tot;
}

// ---------------- host orchestration -------------------------------------------
extern "C" void kernel_launch(void* const* d_in, const int* in_sizes, int n_in,
                              void* d_out, int out_size) {
    const float* x_paper  = (const float*)d_in[0];
    const float* x_author = (const float*)d_in[1];
    const float* lin_w = (const float*)d_in[2];
    const float* lin_b = (const float*)d_in[3];
    const float* k_w = (const float*)d_in[4];
    const float* k_b = (const float*)d_in[5];
    const float* q_w = (const float*)d_in[6];
    const float* q_b = (const float*)d_in[7];
    const float* v_w = (const float*)d_in[8];
    const float* v_b = (const float*)d_in[9];
    const float* a_w = (const float*)d_in[10];
    const float* a_b = (const float*)d_in[11];
    const float* skip  = (const float*)d_in[12];
    const float* a_rel = (const float*)d_in[13];
    const float* m_rel = (const float*)d_in[14];
    const float* p_rel = (const float*)d_in[15];
    const int* srcs[3] = {(const int*)d_in[16], (const int*)d_in[18], (const int*)d_in[20]};
    const int* dsts[3] = {(const int*)d_in[17], (const int*)d_in[19], (const int*)d_in[21]};
    int E[3] = {in_sizes[16], in_sizes[18], in_sizes[20]};

    static cudaStream_t s1 = nullptr;
    static cudaEvent_t ev[4];
    if (!s1) {
        cudaStreamCreateWithFlags(&s1, cudaStreamNonBlocking);
        for (int i = 0; i < 4; i++) cudaEventCreateWithFlags(&ev[i], cudaEventDisableTiming);
        cudaFuncSetAttribute(gemm_mega, cudaFuncAttributeMaxDynamicSharedMemorySize, SM_NEED);
    }
    cudaStream_t s0 = 0;

    void* p;
    float *xb[2], *qb, *agg, *Wk, *Wv, *bk, *bv;
    __half *krel, *vrel;
    uint32_t* wpack;
    int *rowptr[3], *csrc[3], *cnt, *bsum;
    cudaGetSymbolAddress(&p, g_x);    xb[0] = (float*)p; xb[1] = xb[0] + (size_t)(NP + NA) * CDIM;
    cudaGetSymbolAddress(&p, g_q);    qb    = (float*)p;
    cudaGetSymbolAddress(&p, g_krel); krel  = (__half*)p;
    cudaGetSymbolAddress(&p, g_vrel); vrel  = (__half*)p;
    cudaGetSymbolAddress(&p, g_agg);  agg   = (float*)p;
    cudaGetSymbolAddress(&p, g_Wk);   Wk    = (float*)p;
    cudaGetSymbolAddress(&p, g_Wv);   Wv    = (float*)p;
    cudaGetSymbolAddress(&p, g_bk);   bk    = (float*)p;
    cudaGetSymbolAddress(&p, g_bv);   bv    = (float*)p;
    cudaGetSymbolAddress(&p, g_wpack);wpack = (uint32_t*)p;
    cudaGetSymbolAddress(&p, g_rowptr);
    for (int r = 0; r < 3; r++) rowptr[r] = (int*)p + (size_t)r * (NP + 1);
    cudaGetSymbolAddress(&p, g_csrc);
    for (int r = 0; r < 3; r++) csrc[r] = (int*)p + (size_t)r * EMAX;
    cudaGetSymbolAddress(&p, g_cnt);  cnt  = (int*)p;
    cudaGetSymbolAddress(&p, g_bsum); bsum = (int*)p;

    auto slot = [&](int s) { return (const uint4*)(wpack + (size_t)s * SLOT_U32); };

    // ======== fork: CSR build entirely on s1 ========
    cudaEventRecord(ev[0], s0);
    cudaStreamWaitEvent(s1, ev[0], 0);
    for (int r = 0; r < 3; r++) {
        int Nd = (r == 2) ? NA : NP;
        fill_i<<<(Nd + 255) / 256, 256, 0, s1>>>(cnt, 0, Nd);
        hist_k<<<(E[r] + 255) / 256, 256, 0, s1>>>(dsts[r], cnt, E[r]);
        int nb = (Nd + 4095) / 4096;
        scan1<<<nb, 256, 0, s1>>>(cnt, rowptr[r] + 1, bsum, Nd);
        scan2<<<1, 32, 0, s1>>>(bsum, nb);
        scan3<<<(Nd + 255) / 256, 256, 0, s1>>>(rowptr[r], bsum, cnt, Nd);
        csr_fill<<<(E[r] + 255) / 256, 256, 0, s1>>>(srcs[r], dsts[r], cnt, csrc[r], E[r]);
    }
    cudaEventRecord(ev[1], s1);

    // ======== s0: composite weights + pack all 22 slots ========================
    build_comp<<<dim3(CDIM, 3, 2), CDIM, 0, s0>>>(k_w, k_b, v_w, v_b, a_rel, m_rel,
                                                  Wk, bk, Wv, bv);
    {
        PackSrc ps{};
        for (int l = 0; l < 2; l++) {
            int base = l * 10;
            ps.w[base + 0] = q_w + (size_t)(l * 2 + 0) * CC;
            ps.w[base + 1] = q_w + (size_t)(l * 2 + 1) * CC;
            ps.w[base + 2] = Wk + (size_t)(l * 3 + 0) * CC;
            ps.w[base + 3] = Wv + (size_t)(l * 3 + 0) * CC;
            ps.w[base + 4] = Wk + (size_t)(l * 3 + 2) * CC;
            ps.w[base + 5] = Wv + (size_t)(l * 3 + 2) * CC;
            ps.w[base + 6] = Wk + (size_t)(l * 3 + 1) * CC;
            ps.w[base + 7] = Wv + (size_t)(l * 3 + 1) * CC;
            ps.w[base + 8] = a_w + (size_t)(l * 2 + 0) * CC;
            ps.w[base + 9] = a_w + (size_t)(l * 2 + 1) * CC;
        }
        ps.w[20] = lin_w; ps.w[21] = lin_w + CC;
        ps.count = NSLOT;
        pack_weights<<<dim3(NSLOT, 8), 128, 0, s0>>>(ps, wpack);
    }

    auto setKV = [&](GemmSeg& G, int t, int sl, const float* bias, void* out) {
        G.wp[t] = slot(sl); G.bias[t] = bias; G.out[t] = out;
        G.outHalf[t] = 1; G.eop[t] = 0;
    };

    // ======== megaGEMM0: wrapper(relu) chained into L0 q/krel/vrel =============
    {
        GemmSeg P{}, Q{};
        const float* bk0 = bk;                // layer 0
        const float* bv0 = bv;
        P.A = x_paper; P.xold = nullptr; P.skipp = nullptr;
        P.M = NP; P.ntiles = 6; P.chain = 1;
        P.wp[0] = slot(20); P.bias[0] = lin_b; P.out[0] = xb[0]; P.outHalf[0] = 0; P.eop[0] = 1;
        P.wp[1] = slot(0);  P.bias[1] = q_b;   P.out[1] = qb;    P.outHalf[1] = 0; P.eop[1] = 0;
        setKV(P, 2, 2, bk0,            krel);
        setKV(P, 3, 3, bv0,            vrel);
        setKV(P, 4, 4, bk0 + 2 * CDIM, krel + 2 * (size_t)NPC);
        setKV(P, 5, 5, bv0 + 2 * CDIM, vrel + 2 * (size_t)NPC);
        Q.A = x_author; Q.xold = nullptr; Q.skipp = nullptr;
        Q.M = NA; Q.ntiles = 4; Q.chain = 1;
        Q.wp[0] = slot(21); Q.bias[0] = lin_b + CDIM; Q.out[0] = xb[0] + NPC; Q.outHalf[0] = 0; Q.eop[0] = 1;
        Q.wp[1] = slot(1);  Q.bias[1] = q_b + CDIM;   Q.out[1] = qb + NPC;    Q.outHalf[1] = 0; Q.eop[1] = 0;
        setKV(Q, 2, 6, bk0 + CDIM, krel + (size_t)NPC);
        setKV(Q, 3, 7, bv0 + CDIM, vrel + (size_t)NPC);
        gemm_mega<<<CTAS_P + CTAS_A, 256, SM_NEED, s0>>>(P, Q, CTAS_P, 0);
    }

    // CSR must be ready before gathers
    cudaStreamWaitEvent(s0, ev[1], 0);

    // ======== gather L0 ========================================================
    gather_all<<<((NP + NA) * 32 + 255) / 256, 256, 0, s0>>>(
        qb, agg, krel, vrel,
        rowptr[0], csrc[0], rowptr[1], csrc[1], rowptr[2], csrc[2],
        p_rel + 0 * 3 * NH);

    // ======== megaGEMM1: L0 out-proj (gelu+skip) chained into L1 q/krel/vrel ===
    {
        GemmSeg P{}, Q{};
        const float* bk1 = bk + 3 * CDIM;     // layer 1
        const float* bv1 = bv + 3 * CDIM;
        P.A = agg; P.xold = xb[0]; P.skipp = skip + 0;
        P.M = NP; P.ntiles = 6; P.chain = 1;
        P.wp[0] = slot(8);  P.bias[0] = a_b;            P.out[0] = xb[1]; P.outHalf[0] = 0; P.eop[0] = 2;
        P.wp[1] = slot(10); P.bias[1] = q_b + 2 * CDIM; P.out[1] = qb;    P.outHalf[1] = 0; P.eop[1] = 0;
        setKV(P, 2, 12, bk1,            krel);
        setKV(P, 3, 13, bv1,            vrel);
        setKV(P, 4, 14, bk1 + 2 * CDIM, krel + 2 * (size_t)NPC);
        setKV(P, 5, 15, bv1 + 2 * CDIM, vrel + 2 * (size_t)NPC);
        Q.A = agg + NPC; Q.xold = xb[0] + NPC; Q.skipp = skip + 1;
        Q.M = NA; Q.ntiles = 4; Q.chain = 1;
        Q.wp[0] = slot(9);  Q.bias[0] = a_b + CDIM;     Q.out[0] = xb[1] + NPC; Q.outHalf[0] = 0; Q.eop[0] = 2;
        Q.wp[1] = slot(11); Q.bias[1] = q_b + 3 * CDIM; Q.out[1] = qb + NPC;    Q.outHalf[1] = 0; Q.eop[1] = 0;
        setKV(Q, 2, 16, bk1 + CDIM, krel + (size_t)NPC);
        setKV(Q, 3, 17, bv1 + CDIM, vrel + (size_t)NPC);
        gemm_mega<<<CTAS_P + CTAS_A, 256, SM_NEED, s0>>>(P, Q, CTAS_P, 1);
    }

    // ======== gather L1 ========================================================
    gather_all<<<((NP + NA) * 32 + 255) / 256, 256, 0, s0>>>(
        qb, agg, krel, vrel,
        rowptr[0], csrc[0], rowptr[1], csrc[1], rowptr[2], csrc[2],
        p_rel + 1 * 3 * NH);

    // ======== final: L1 out-proj (gelu+skip) -> d_out ==========================
    {
        GemmSeg P{}, Q{};
        P.A = agg; P.xold = xb[1]; P.skipp = skip + 2;
        P.M = NP; P.ntiles = 1; P.chain = 0;
        P.wp[0] = slot(18); P.bias[0] = a_b + 2 * CDIM; P.out[0] = (float*)d_out;
        P.outHalf[0] = 0; P.eop[0] = 2;
        Q.A = agg + NPC; Q.xold = xb[1] + NPC; Q.skipp = skip + 3;
        Q.M = NA; Q.ntiles = 1; Q.chain = 0;
        Q.wp[0] = slot(19); Q.bias[0] = a_b + 3 * CDIM; Q.out[0] = (float*)d_out + NPC;
        Q.outHalf[0] = 0; Q.eop[0] = 2;
        gemm_mega<<<CTAS_P + CTAS_A, 256, SM_NEED, s0>>>(P, Q, CTAS_P, 1);
    }
}

// round 12
// speedup vs baseline: 1.1845x; 1.0360x over previous
#include <cuda_runtime.h>
#include <cuda_fp16.h>
#include <math.h>
#include <stdint.h>

#define NP 100000
#define NA 50000
#define CDIM 128
#define CC (CDIM*CDIM)
#define NH 4
#define NPC (NP*CDIM)
#define EMAX 300000

#define PITCH 136                 // fp16 per row in staged images
#define PITCHB 272                // bytes
#define A_IMG 17408               // 64 rows * 272B
#define B_IMG 34816               // 128 rows * 272B
#define SLOT_U32 8704             // one B image = 8704 u32 per slot
#define NSLOT 22                  // 0-9 layer0, 10-19 layer1, 20-21 wrapper
#define CTAS_P ((NP+63)/64)
#define CTAS_A ((NA+63)/64)

// ---------------- scratch (device globals) -----------------------------------
__device__ float  g_x[2][(NP+NA)*CDIM];
__device__ __half g_q[(NP+NA)*CDIM];
__device__ __half g_krel[3][NPC];
__device__ __half g_vrel[3][NPC];
__device__ __half g_agg[(NP+NA)*CDIM];     // holds gelu(agg), fp16
__device__ float  g_Wk[2][3][CC];
__device__ float  g_Wv[2][3][CC];
__device__ float  g_bk[2][3][CDIM];
__device__ float  g_bv[2][3][CDIM];
__device__ uint32_t g_wpack[NSLOT][SLOT_U32];
__device__ int g_rowptr[3][NP+1];
__device__ int g_csrc[3][EMAX];
__device__ int g_cnt[NP];
__device__ int g_bsum[64];

// ---------------- small helpers ----------------------------------------------
__device__ __forceinline__ float gelu_f(float x) {
    return 0.5f * x * (1.0f + erff(x * 0.7071067811865476f));
}
__global__ void fill_i(int* __restrict__ p, int v, int n) {
    int i = blockIdx.x * blockDim.x + threadIdx.x;
    if (i < n) p[i] = v;
}
__global__ void hist_k(const int* __restrict__ dst, int* __restrict__ cnt, int E) {
    int i = blockIdx.x * blockDim.x + threadIdx.x;
    if (i < E) atomicAdd(&cnt[dst[i]], 1);
}
__global__ void scan1(const int* __restrict__ cnt, int* __restrict__ rp1,
                      int* __restrict__ bsum, int n) {
    __shared__ int sm[256];
    int base = blockIdx.x * 4096;
    int idx0 = base + threadIdx.x * 16;
    int v[16]; int t = 0;
#pragma unroll
    for (int j = 0; j < 16; j++) { int ix = idx0 + j; v[j] = (ix < n) ? cnt[ix] : 0; t += v[j]; }
    sm[threadIdx.x] = t;
    __syncthreads();
    for (int off = 1; off < 256; off <<= 1) {
        int x = 0;
        if ((int)threadIdx.x >= off) x = sm[threadIdx.x - off];
        __syncthreads();
        if ((int)threadIdx.x >= off) sm[threadIdx.x] += x;
        __syncthreads();
    }
    int run = sm[threadIdx.x] - t;
#pragma unroll
    for (int j = 0; j < 16; j++) { run += v[j]; int ix = idx0 + j; if (ix < n) rp1[ix] = run; }
    if (threadIdx.x == 255) bsum[blockIdx.x] = sm[255];
}
__global__ void scan2(int* __restrict__ bsum, int nb) {
    int tid = threadIdx.x;
    int orig = (tid < nb) ? bsum[tid] : 0;
    int v = orig;
    for (int off = 1; off < 32; off <<= 1) {
        int x = __shfl_up_sync(0xffffffffu, v, off);
        if (tid >= off) v += x;
    }
    if (tid < nb) bsum[tid] = v - orig;
}
__global__ void scan3(int* __restrict__ rowptr, const int* __restrict__ bsum,
                      int* __restrict__ cursor, int n) {
    int i = blockIdx.x * blockDim.x + threadIdx.x;
    if (i < n) {
        int val = rowptr[i + 1] + bsum[i >> 12];
        rowptr[i + 1] = val;
        if (i + 1 < n) cursor[i + 1] = val;
    }
    if (i == 0) { rowptr[0] = 0; cursor[0] = 0; }
}
__global__ void csr_fill(const int* __restrict__ src, const int* __restrict__ dst,
                         int* __restrict__ cursor, int* __restrict__ csrc, int E) {
    int i = blockIdx.x * blockDim.x + threadIdx.x;
    if (i >= E) return;
    int pos = atomicAdd(&cursor[dst[i]], 1);
    csrc[pos] = src[i];
}

// ---------------- PTX helpers -------------------------------------------------
__device__ __forceinline__ uint32_t smem_u32(const void* p) {
    uint32_t a;
    asm("{ .reg .u64 t; cvta.to.shared.u64 t, %1; cvt.u32.u64 %0, t; }" : "=r"(a) : "l"(p));
    return a;
}
__device__ __forceinline__ uint32_t pk_h2(__half a, __half b) {
    __half2 t = __halves2half2(a, b);
    return *reinterpret_cast<uint32_t*>(&t);
}
__device__ __forceinline__ void ldsm4(uint32_t* r, uint32_t addr) {
    asm volatile("ldmatrix.sync.aligned.m8n8.x4.shared.b16 {%0,%1,%2,%3}, [%4];"
        : "=r"(r[0]), "=r"(r[1]), "=r"(r[2]), "=r"(r[3]) : "r"(addr));
}
__device__ __forceinline__ void mma16816(float* c, const uint32_t* a, const uint32_t* b) {
    asm volatile("mma.sync.aligned.m16n8k16.row.col.f32.f16.f16.f32 "
        "{%0,%1,%2,%3}, {%4,%5,%6,%7}, {%8,%9}, {%0,%1,%2,%3};"
        : "+f"(c[0]), "+f"(c[1]), "+f"(c[2]), "+f"(c[3])
        : "r"(a[0]), "r"(a[1]), "r"(a[2]), "r"(a[3]), "r"(b[0]), "r"(b[1]));
}
__device__ __forceinline__ void cp16(uint32_t dst, const void* src) {
    asm volatile("cp.async.cg.shared.global [%0], [%1], 16;" :: "r"(dst), "l"(src));
}

// ---------------- weight packing: fp32 -> pitched fp16 -------------------------
struct PackSrc { const float* w[NSLOT]; int count; };
__global__ void pack_weights(PackSrc ps, uint32_t* dstbase) {
    int m = blockIdx.x;
    if (m >= ps.count) return;
    const float* W = ps.w[m];
    uint32_t* hi = dstbase + (size_t)m * SLOT_U32;
    int n = threadIdx.x;
    int k0 = blockIdx.y * 16;
    for (int k = k0; k < k0 + 16; k += 2) {
        hi[n * (PITCH / 2) + (k >> 1)] =
            pk_h2(__float2half_rn(W[k * 128 + n]), __float2half_rn(W[(k + 1) * 128 + n]));
    }
}

// ---------------- composite relation weights (both layers) ---------------------
__global__ void build_comp(const float* __restrict__ kw0, const float* __restrict__ kb0,
                           const float* __restrict__ vw0, const float* __restrict__ vb0,
                           const float* __restrict__ arel0, const float* __restrict__ mrel0,
                           float* __restrict__ Wk0, float* __restrict__ bk0,
                           float* __restrict__ Wv0, float* __restrict__ bv0) {
    int c = blockIdx.x, r = blockIdx.y, l = blockIdx.z, j = threadIdx.x;
    const float* kw = kw0 + (size_t)l * 2 * CC;
    const float* kb = kb0 + l * 2 * CDIM;
    const float* vw = vw0 + (size_t)l * 2 * CC;
    const float* vb = vb0 + l * 2 * CDIM;
    const float* arel = arel0 + (size_t)l * 3 * NH * 1024;
    const float* mrel = mrel0 + (size_t)l * 3 * NH * 1024;
    float* Wk = Wk0 + (size_t)l * 3 * CC;
    float* Wv = Wv0 + (size_t)l * 3 * CC;
    float* bk = bk0 + l * 3 * CDIM;
    float* bv = bv0 + l * 3 * CDIM;
    int st = (r == 1) ? 1 : 0;
    int h = j >> 5, e = j & 31;
    const float* kwp = kw + ((size_t)st * CDIM + c) * CDIM + h * 32;
    const float* vwp = vw + ((size_t)st * CDIM + c) * CDIM + h * 32;
    const float* ap  = arel + (size_t)(r * NH + h) * 1024 + e;
    const float* mp  = mrel + (size_t)(r * NH + h) * 1024 + e;
    float sk = 0.f, sv = 0.f;
#pragma unroll
    for (int d = 0; d < 32; d++) {
        sk += kwp[d] * ap[d * 32];
        sv += vwp[d] * mp[d * 32];
    }
    Wk[(size_t)r * CC + (size_t)c * CDIM + j] = sk;
    Wv[(size_t)r * CC + (size_t)c * CDIM + j] = sv;
    if (c == 0) {
        float bks = 0.f, bvs = 0.f;
        const float* kbp = kb + st * CDIM + h * 32;
        const float* vbp = vb + st * CDIM + h * 32;
#pragma unroll
        for (int d = 0; d < 32; d++) {
            bks += kbp[d] * ap[d * 32];
            bvs += vbp[d] * mp[d * 32];
        }
        bk[r * CDIM + j] = bks;
        bv[r * CDIM + j] = bvs;
    }
}

// ---------------- segmented chained mega-GEMM ----------------------------------
struct GemmSeg {
    const void*  A;        // fp32 or fp16 per aHalf
    const float* xold;     // for eop==2 tiles (fp32)
    const float* skipp;
    int M;
    int ntiles;
    int chain;             // 1: tile0 output re-staged as new A
    int aHalf;             // 1: A is fp16 (pure copy stage)
    const uint4* wp[6];
    const float* bias[6];
    void*        out[6];
    int          outHalf[6];
    int          eop[6];   // 0 +bias, 1 relu, 2 skip-blend
};

#define SM_A     0
#define SM_B(b)  (A_IMG + (b)*B_IMG)
#define SM_NEED  (A_IMG + 2*B_IMG)       // 87040 bytes -> 2 CTAs/SM

__device__ __forceinline__ void prefetch_B(uint32_t dstb, const uint4* src, int tid) {
#pragma unroll
    for (int i = 0; i < 8; i++) cp16(dstb + (uint32_t)(i * 256 + tid) * 16, src + i * 256 + tid);
    if (tid < 128) cp16(dstb + (uint32_t)(2048 + tid) * 16, src + 2048 + tid);
    asm volatile("cp.async.commit_group;" ::: "memory");
}

__global__ void __launch_bounds__(256, 2)
gemm_mega(GemmSeg P0, GemmSeg P1, int ctas0) {
    extern __shared__ char sm[];
    uint32_t sb = smem_u32(sm);
    int tid = threadIdx.x, lane = tid & 31, wid = tid >> 5;
    int wm = wid & 1, wn = wid >> 1;
    int bx = blockIdx.x;
    bool seg1 = bx >= ctas0;
    const GemmSeg& P = seg1 ? P1 : P0;
    int rowBase = (seg1 ? bx - ctas0 : bx) * 64;
    int M = P.M;

    prefetch_B(sb + SM_B(0), P.wp[0], tid);

    // ---- stage A ----
    if (P.aHalf) {
        const __half* Ah = (const __half*)P.A;
#pragma unroll
        for (int it = 0; it < 4; it++) {
            int f = it * 256 + tid;
            int m = f >> 4, c = f & 15;
            int row = rowBase + m;
            uint4 v = make_uint4(0, 0, 0, 0);
            if (row < M) v = *(const uint4*)(Ah + (size_t)row * CDIM + c * 8);
            *(uint4*)(sm + SM_A + m * PITCHB + c * 16) = v;
        }
    } else {
        const float* Af = (const float*)P.A;
#pragma unroll 4
        for (int it = 0; it < 8; it++) {
            int f = it * 256 + tid;
            int m = f >> 5, k = (f & 31) << 2;
            int row = rowBase + m;
            float4 v = make_float4(0.f, 0.f, 0.f, 0.f);
            if (row < M) v = *(const float4*)(Af + (size_t)row * CDIM + k);
            uint32_t off = (uint32_t)(m * PITCHB + k * 2);
            *(uint2*)(sm + SM_A + off) = make_uint2(
                pk_h2(__float2half_rn(v.x), __float2half_rn(v.y)),
                pk_h2(__float2half_rn(v.z), __float2half_rn(v.w)));
        }
    }

    int aRow = wm * 32 + (lane & 15);
    uint32_t aKoff = (lane & 16) ? 16u : 0u;
    uint32_t aBase = sb + SM_A + aRow * PITCHB + aKoff;
    int bN = wn * 32 + (lane & 7) + ((lane & 16) ? 8 : 0);
    uint32_t bKoff = (lane & 8) ? 16u : 0u;
    uint32_t bOff = bN * PITCHB + bKoff;

    float skv = 0.f;
    if (P.skipp) skv = 1.f / (1.f + expf(-*P.skipp));
    int g = lane >> 2, tg = lane & 3;
    int nt = P.ntiles;

    for (int b = 0; b < nt; b++) {
        if (b + 1 < nt) {
            prefetch_B(sb + SM_B((b + 1) & 1), P.wp[b + 1], tid);
            asm volatile("cp.async.wait_group 1;" ::: "memory");
        } else {
            asm volatile("cp.async.wait_group 0;" ::: "memory");
        }
        __syncthreads();

        float acc[2][4][4];
#pragma unroll
        for (int i = 0; i < 2; i++)
#pragma unroll
            for (int j = 0; j < 4; j++)
#pragma unroll
                for (int q = 0; q < 4; q++) acc[i][j][q] = 0.f;

        uint32_t aCur = aBase, bHi = sb + SM_B(b & 1) + bOff;
#pragma unroll
        for (int ks = 0; ks < 8; ks++) {
            uint32_t ah[2][4], bh[2][4];
            ldsm4(ah[0], aCur); ldsm4(ah[1], aCur + 16 * PITCHB);
            ldsm4(bh[0], bHi);  ldsm4(bh[1], bHi + 16 * PITCHB);
#pragma unroll
            for (int i = 0; i < 2; i++)
#pragma unroll
                for (int j = 0; j < 4; j++)
                    mma16816(acc[i][j], ah[i], &bh[j >> 1][(j & 1) * 2]);
            aCur += 32; bHi += 32;
        }
        __syncthreads();

        const float* bias = P.bias[b];
        int eop = P.eop[b];
        int oh = P.outHalf[b];
        bool chain0 = (b == 0) && P.chain;
        float* outF = (float*)P.out[b];
        __half* outH = (__half*)P.out[b];
#pragma unroll
        for (int i = 0; i < 2; i++) {
            int r0 = rowBase + wm * 32 + i * 16 + g;
#pragma unroll
            for (int j = 0; j < 4; j++) {
                int col = wn * 32 + j * 8 + tg * 2;
                float b0 = bias[col], b1 = bias[col + 1];
#pragma unroll
                for (int half = 0; half < 2; half++) {
                    int row = r0 + half * 8;
                    if (row >= M) continue;
                    float v0 = acc[i][j][half * 2 + 0] + b0;
                    float v1 = acc[i][j][half * 2 + 1] + b1;
                    if (eop == 1) {
                        v0 = fmaxf(v0, 0.f); v1 = fmaxf(v1, 0.f);
                    } else if (eop == 2) {
                        float2 xo = *(const float2*)(P.xold + (size_t)row * CDIM + col);
                        v0 = skv * v0 + (1.f - skv) * xo.x;
                        v1 = skv * v1 + (1.f - skv) * xo.y;
                    }
                    if (oh) {
                        *(__half2*)(outH + (size_t)row * CDIM + col) = __floats2half2_rn(v0, v1);
                    } else {
                        *(float2*)(outF + (size_t)row * CDIM + col) = make_float2(v0, v1);
                    }
                    if (chain0) {
                        uint32_t off = (uint32_t)((row - rowBase) * PITCHB + col * 2);
                        *(__half2*)(sm + SM_A + off) = __floats2half2_rn(v0, v1);
                    }
                }
            }
        }
    }
}

// ---------------- merged edge gather: fp16 q/k/v, writes gelu(agg) fp16 --------
__device__ __forceinline__ float4 ld_half4(const __half* base, size_t off) {
    uint2 raw = *(const uint2*)(base + off);
    __half2* ph = (__half2*)&raw;
    float2 a = __half22float2(ph[0]);
    float2 b = __half22float2(ph[1]);
    return make_float4(a.x, a.y, b.x, b.y);
}

__global__ void __launch_bounds__(256)
gather_all(const __half* __restrict__ q, __half* __restrict__ agg,
           const __half* __restrict__ krel, const __half* __restrict__ vrel,
           const int* __restrict__ rp0, const int* __restrict__ cs0,
           const int* __restrict__ rp1, const int* __restrict__ cs1,
           const int* __restrict__ rp2, const int* __restrict__ cs2,
           const float* __restrict__ prel) {
    int w = (blockIdx.x * blockDim.x + threadIdx.x) >> 5;
    if (w >= NP + NA) return;
    int lane = threadIdx.x & 31;
    int h = lane >> 3;
    float4 qv = ld_half4(q, (size_t)w * CDIM + lane * 4);
    float4 tot = make_float4(0.f, 0.f, 0.f, 0.f);
    int nrel, node;
    const int* rps[2]; const int* css[2]; int rr[2];
    if (w < NP) {
        nrel = 2; node = w;
        rps[0] = rp0; css[0] = cs0; rr[0] = 0;
        rps[1] = rp1; css[1] = cs1; rr[1] = 1;
    } else {
        nrel = 1; node = w - NP;
        rps[0] = rp2; css[0] = cs2; rr[0] = 2;
        rps[1] = rp2; css[1] = cs2; rr[1] = 2;
    }
    for (int rel = 0; rel < nrel; rel++) {
        const __half* kr = krel + (size_t)rr[rel] * NPC;
        const __half* vr = vrel + (size_t)rr[rel] * NPC;
        const int* rp = rps[rel];
        const int* cs = css[rel];
        float pscale = prel[rr[rel] * NH + h] * 0.17677669529663687f;
        int beg = rp[node], end = rp[node + 1];
        float m = -INFINITY, s = 0.f;
        float4 acc = make_float4(0.f, 0.f, 0.f, 0.f);
        float4 kv, vv;
        if (beg < end) {
            int sidx = cs[beg];
            kv = ld_half4(kr, (size_t)sidx * CDIM + lane * 4);
            vv = ld_half4(vr, (size_t)sidx * CDIM + lane * 4);
        }
        for (int e = beg; e < end; e++) {
            float4 kn, vn;
            if (e + 1 < end) {
                int sn = cs[e + 1];
                kn = ld_half4(kr, (size_t)sn * CDIM + lane * 4);
                vn = ld_half4(vr, (size_t)sn * CDIM + lane * 4);
            }
            float dot = qv.x * kv.x + qv.y * kv.y + qv.z * kv.z + qv.w * kv.w;
            dot += __shfl_xor_sync(0xffffffffu, dot, 1);
            dot += __shfl_xor_sync(0xffffffffu, dot, 2);
            dot += __shfl_xor_sync(0xffffffffu, dot, 4);
            float alpha = dot * pscale;
            float mn = fmaxf(m, alpha);
            float sc = __expf(m - mn);
            float p = __expf(alpha - mn);
            s = s * sc + p;
            acc.x = acc.x * sc + p * vv.x;
            acc.y = acc.y * sc + p * vv.y;
            acc.z = acc.z * sc + p * vv.z;
            acc.w = acc.w * sc + p * vv.w;
            m = mn;
            kv = kn; vv = vn;
        }
        float inv = 1.f / (s + 1e-16f);
        tot.x += acc.x * inv; tot.y += acc.y * inv;
        tot.z += acc.z * inv; tot.w += acc.w * inv;
    }
    uint2 outv;
    outv.x = pk_h2(__float2half_rn(gelu_f(tot.x)), __float2half_rn(gelu_f(tot.y)));
    outv.y = pk_h2(__float2half_rn(gelu_f(tot.z)), __float2half_rn(gelu_f(tot.w)));
    *(uint2*)(agg + (size_t)w * CDIM + lane * 4) = outv;
}

// ---------------- host orchestration -------------------------------------------
extern "C" void kernel_launch(void* const* d_in, const int* in_sizes, int n_in,
                              void* d_out, int out_size) {
    const float* x_paper  = (const float*)d_in[0];
    const float* x_author = (const float*)d_in[1];
    const float* lin_w = (const float*)d_in[2];
    const float* lin_b = (const float*)d_in[3];
    const float* k_w = (const float*)d_in[4];
    const float* k_b = (const float*)d_in[5];
    const float* q_w = (const float*)d_in[6];
    const float* q_b = (const float*)d_in[7];
    const float* v_w = (const float*)d_in[8];
    const float* v_b = (const float*)d_in[9];
    const float* a_w = (const float*)d_in[10];
    const float* a_b = (const float*)d_in[11];
    const float* skip  = (const float*)d_in[12];
    const float* a_rel = (const float*)d_in[13];
    const float* m_rel = (const float*)d_in[14];
    const float* p_rel = (const float*)d_in[15];
    const int* srcs[3] = {(const int*)d_in[16], (const int*)d_in[18], (const int*)d_in[20]};
    const int* dsts[3] = {(const int*)d_in[17], (const int*)d_in[19], (const int*)d_in[21]};
    int E[3] = {in_sizes[16], in_sizes[18], in_sizes[20]};

    static cudaStream_t s1 = nullptr;
    static cudaEvent_t ev[2];
    if (!s1) {
        cudaStreamCreateWithFlags(&s1, cudaStreamNonBlocking);
        for (int i = 0; i < 2; i++) cudaEventCreateWithFlags(&ev[i], cudaEventDisableTiming);
        cudaFuncSetAttribute(gemm_mega, cudaFuncAttributeMaxDynamicSharedMemorySize, SM_NEED);
    }
    cudaStream_t s0 = 0;

    void* p;
    float *xb[2], *Wk, *Wv, *bk, *bv;
    __half *qb, *krel, *vrel, *agg;
    uint32_t* wpack;
    int *rowptr[3], *csrc[3], *cnt, *bsum;
    cudaGetSymbolAddress(&p, g_x);    xb[0] = (float*)p; xb[1] = xb[0] + (size_t)(NP + NA) * CDIM;
    cudaGetSymbolAddress(&p, g_q);    qb    = (__half*)p;
    cudaGetSymbolAddress(&p, g_krel); krel  = (__half*)p;
    cudaGetSymbolAddress(&p, g_vrel); vrel  = (__half*)p;
    cudaGetSymbolAddress(&p, g_agg);  agg   = (__half*)p;
    cudaGetSymbolAddress(&p, g_Wk);   Wk    = (float*)p;
    cudaGetSymbolAddress(&p, g_Wv);   Wv    = (float*)p;
    cudaGetSymbolAddress(&p, g_bk);   bk    = (float*)p;
    cudaGetSymbolAddress(&p, g_bv);   bv    = (float*)p;
    cudaGetSymbolAddress(&p, g_wpack);wpack = (uint32_t*)p;
    cudaGetSymbolAddress(&p, g_rowptr);
    for (int r = 0; r < 3; r++) rowptr[r] = (int*)p + (size_t)r * (NP + 1);
    cudaGetSymbolAddress(&p, g_csrc);
    for (int r = 0; r < 3; r++) csrc[r] = (int*)p + (size_t)r * EMAX;
    cudaGetSymbolAddress(&p, g_cnt);  cnt  = (int*)p;
    cudaGetSymbolAddress(&p, g_bsum); bsum = (int*)p;

    auto slot = [&](int s) { return (const uint4*)(wpack + (size_t)s * SLOT_U32); };
    auto setKV = [&](GemmSeg& G, int t, int sl, const float* bias, void* out) {
        G.wp[t] = slot(sl); G.bias[t] = bias; G.out[t] = out;
        G.outHalf[t] = 1; G.eop[t] = 0;
    };

    // ==== fork s1 from capture-origin stream (REQUIRED for graph capture) =====
    cudaEventRecord(ev[0], s0);
    cudaStreamWaitEvent(s1, ev[0], 0);

    // ==== kernel launch order: build_comp(1), pack(2), fill_i(3), mega0(4) ====
    build_comp<<<dim3(CDIM, 3, 2), CDIM, 0, s0>>>(k_w, k_b, v_w, v_b, a_rel, m_rel,
                                                  Wk, bk, Wv, bv);
    {
        PackSrc ps{};
        for (int l = 0; l < 2; l++) {
            int base = l * 10;
            ps.w[base + 0] = q_w + (size_t)(l * 2 + 0) * CC;
            ps.w[base + 1] = q_w + (size_t)(l * 2 + 1) * CC;
            ps.w[base + 2] = Wk + (size_t)(l * 3 + 0) * CC;
            ps.w[base + 3] = Wv + (size_t)(l * 3 + 0) * CC;
            ps.w[base + 4] = Wk + (size_t)(l * 3 + 2) * CC;
            ps.w[base + 5] = Wv + (size_t)(l * 3 + 2) * CC;
            ps.w[base + 6] = Wk + (size_t)(l * 3 + 1) * CC;
            ps.w[base + 7] = Wv + (size_t)(l * 3 + 1) * CC;
            ps.w[base + 8] = a_w + (size_t)(l * 2 + 0) * CC;
            ps.w[base + 9] = a_w + (size_t)(l * 2 + 1) * CC;
        }
        ps.w[20] = lin_w; ps.w[21] = lin_w + CC;
        ps.count = NSLOT;
        pack_weights<<<dim3(NSLOT, 8), 128, 0, s0>>>(ps, wpack);
    }
    fill_i<<<(NP + 255) / 256, 256, 0, s1>>>(cnt, 0, NP);   // CSR r=0 start (s1)

    // megaGEMM0: wrapper(relu) chained into L0 q/krel/vrel
    {
        GemmSeg P{}, Q{};
        const float* bk0 = bk;
        const float* bv0 = bv;
        P.A = x_paper; P.xold = nullptr; P.skipp = nullptr;
        P.M = NP; P.ntiles = 6; P.chain = 1; P.aHalf = 0;
        P.wp[0] = slot(20); P.bias[0] = lin_b; P.out[0] = xb[0]; P.outHalf[0] = 0; P.eop[0] = 1;
        setKV(P, 1, 0, q_b, qb);
        setKV(P, 2, 2, bk0,            krel);
        setKV(P, 3, 3, bv0,            vrel);
        setKV(P, 4, 4, bk0 + 2 * CDIM, krel + 2 * (size_t)NPC);
        setKV(P, 5, 5, bv0 + 2 * CDIM, vrel + 2 * (size_t)NPC);
        Q.A = x_author; Q.xold = nullptr; Q.skipp = nullptr;
        Q.M = NA; Q.ntiles = 4; Q.chain = 1; Q.aHalf = 0;
        Q.wp[0] = slot(21); Q.bias[0] = lin_b + CDIM; Q.out[0] = xb[0] + NPC; Q.outHalf[0] = 0; Q.eop[0] = 1;
        setKV(Q, 1, 1, q_b + CDIM, qb + NPC);
        setKV(Q, 2, 6, bk0 + CDIM, krel + (size_t)NPC);
        setKV(Q, 3, 7, bv0 + CDIM, vrel + (size_t)NPC);
        gemm_mega<<<CTAS_P + CTAS_A, 256, SM_NEED, s0>>>(P, Q, CTAS_P);
    }

    // rest of CSR build on s1 (concurrent with mega0)
    {
        int r = 0;
        int Nd = NP;
        hist_k<<<(E[r] + 255) / 256, 256, 0, s1>>>(dsts[r], cnt, E[r]);
        int nb = (Nd + 4095) / 4096;
        scan1<<<nb, 256, 0, s1>>>(cnt, rowptr[r] + 1, bsum, Nd);
        scan2<<<1, 32, 0, s1>>>(bsum, nb);
        scan3<<<(Nd + 255) / 256, 256, 0, s1>>>(rowptr[r], bsum, cnt, Nd);
        csr_fill<<<(E[r] + 255) / 256, 256, 0, s1>>>(srcs[r], dsts[r], cnt, csrc[r], E[r]);
    }
    for (int r = 1; r < 3; r++) {
        int Nd = (r == 2) ? NA : NP;
        fill_i<<<(Nd + 255) / 256, 256, 0, s1>>>(cnt, 0, Nd);
        hist_k<<<(E[r] + 255) / 256, 256, 0, s1>>>(dsts[r], cnt, E[r]);
        int nb = (Nd + 4095) / 4096;
        scan1<<<nb, 256, 0, s1>>>(cnt, rowptr[r] + 1, bsum, Nd);
        scan2<<<1, 32, 0, s1>>>(bsum, nb);
        scan3<<<(Nd + 255) / 256, 256, 0, s1>>>(rowptr[r], bsum, cnt, Nd);
        csr_fill<<<(E[r] + 255) / 256, 256, 0, s1>>>(srcs[r], dsts[r], cnt, csrc[r], E[r]);
    }
    cudaEventRecord(ev[1], s1);
    cudaStreamWaitEvent(s0, ev[1], 0);

    // gather L0
    gather_all<<<((NP + NA) * 32 + 255) / 256, 256, 0, s0>>>(
        qb, agg, krel, vrel,
        rowptr[0], csrc[0], rowptr[1], csrc[1], rowptr[2], csrc[2],
        p_rel + 0 * 3 * NH);

    // megaGEMM1: L0 out-proj (skip-blend; A=gelu(agg) fp16) chained into L1 q/k/v
    {
        GemmSeg P{}, Q{};
        const float* bk1 = bk + 3 * CDIM;
        const float* bv1 = bv + 3 * CDIM;
        P.A = agg; P.xold = xb[0]; P.skipp = skip + 0;
        P.M = NP; P.ntiles = 6; P.chain = 1; P.aHalf = 1;
        P.wp[0] = slot(8);  P.bias[0] = a_b; P.out[0] = xb[1]; P.outHalf[0] = 0; P.eop[0] = 2;
        setKV(P, 1, 10, q_b + 2 * CDIM, qb);
        setKV(P, 2, 12, bk1,            krel);
        setKV(P, 3, 13, bv1,            vrel);
        setKV(P, 4, 14, bk1 + 2 * CDIM, krel + 2 * (size_t)NPC);
        setKV(P, 5, 15, bv1 + 2 * CDIM, vrel + 2 * (size_t)NPC);
        Q.A = agg + NPC; Q.xold = xb[0] + NPC; Q.skipp = skip + 1;
        Q.M = NA; Q.ntiles = 4; Q.chain = 1; Q.aHalf = 1;
        Q.wp[0] = slot(9); Q.bias[0] = a_b + CDIM; Q.out[0] = xb[1] + NPC; Q.outHalf[0] = 0; Q.eop[0] = 2;
        setKV(Q, 1, 11, q_b + 3 * CDIM, qb + NPC);
        setKV(Q, 2, 16, bk1 + CDIM, krel + (size_t)NPC);
        setKV(Q, 3, 17, bv1 + CDIM, vrel + (size_t)NPC);
        gemm_mega<<<CTAS_P + CTAS_A, 256, SM_NEED, s0>>>(P, Q, CTAS_P);
    }

    // gather L1
    gather_all<<<((NP + NA) * 32 + 255) / 256, 256, 0, s0>>>(
        qb, agg, krel, vrel,
        rowptr[0], csrc[0], rowptr[1], csrc[1], rowptr[2], csrc[2],
        p_rel + 1 * 3 * NH);

    // final: L1 out-proj (skip-blend) -> d_out
    {
        GemmSeg P{}, Q{};
        P.A = agg; P.xold = xb[1]; P.skipp = skip + 2;
        P.M = NP; P.ntiles = 1; P.chain = 0; P.aHalf = 1;
        P.wp[0] = slot(18); P.bias[0] = a_b + 2 * CDIM; P.out[0] = (float*)d_out;
        P.outHalf[0] = 0; P.eop[0] = 2;
        Q.A = agg + NPC; Q.xold = xb[1] + NPC; Q.skipp = skip + 3;
        Q.M = NA; Q.ntiles = 1; Q.chain = 0; Q.aHalf = 1;
        Q.wp[0] = slot(19); Q.bias[0] = a_b + 3 * CDIM; Q.out[0] = (float*)d_out + NPC;
        Q.outHalf[0] = 0; Q.eop[0] = 2;
        gemm_mega<<<CTAS_P + CTAS_A, 256, SM_NEED, s0>>>(P, Q, CTAS_P);
    }
}